// round 9
// baseline (speedup 1.0000x reference)
#include <cuda_runtime.h>
#include <cuda_bf16.h>
#include <math_constants.h>
#include <cstdint>

// Problem constants (fixed by the dataset)
#define NN   50000
#define EE   800000
#define E2   (EE + NN)      // edges + self loops = 850000
#define FIN  512
#define H1   8
#define C1   32
#define D1   (H1 * C1)      // 256
#define CLS  40

// ---------------- scratch (static device globals; no runtime alloc) ----------
__device__ float g_h1[NN * D1];          // layer1 linear output [N,256]
__device__ float g_as1[NN * H1];
__device__ float g_ad1[NN * H1];
__device__ float g_deninv[NN * H1];      // reciprocal softmax denominators (layer1)
__device__ float g_hout1[NN * D1];       // elu(agg1 + b1) [N,256]
__device__ float g_h2lin[NN * CLS];
__device__ float g_as2[NN];
__device__ float g_ad2[NN];
__device__ float g_wbuf[H1 * E2];        // per-head planes: [h][edge]
__device__ float g_wbuf2[E2];
__device__ int   g_deg[NN];
__device__ int   g_incl[NN];
__device__ int   g_starts[NN];
__device__ int   g_cursor[NN];
__device__ int   g_ssrc[E2];
__device__ int   g_parts[64];
__device__ int   g_parts_ex[64];
// bf16 split-precision operands for GEMM1
__device__ uint32_t g_xhi[NN * (FIN / 2)];
__device__ uint32_t g_xlo[NN * (FIN / 2)];
__device__ uint32_t g_w1t_hi[D1 * (FIN / 2)];
__device__ uint32_t g_w1t_lo[D1 * (FIN / 2)];

// ---------------- bf16 split helpers -----------------------------------------
__device__ __forceinline__ void split2(float x, float y, uint32_t& hi, uint32_t& lo) {
    __nv_bfloat16 hx = __float2bfloat16_rn(x);
    __nv_bfloat16 hy = __float2bfloat16_rn(y);
    float lxf = x - __bfloat162float(hx);
    float lyf = y - __bfloat162float(hy);
    __nv_bfloat162 hv; hv.x = hx; hv.y = hy;
    __nv_bfloat162 lv = __floats2bfloat162_rn(lxf, lyf);
    hi = *reinterpret_cast<uint32_t*>(&hv);
    lo = *reinterpret_cast<uint32_t*>(&lv);
}

__global__ void prep_x_kernel(const float* __restrict__ x) {
    int i = blockIdx.x * blockDim.x + threadIdx.x;
    const int NQ = NN * FIN / 4;
    if (i >= NQ) return;
    float4 v = ((const float4*)x)[i];
    uint32_t h0, l0, h1, l1;
    split2(v.x, v.y, h0, l0);
    split2(v.z, v.w, h1, l1);
    g_xhi[2 * i]     = h0;  g_xhi[2 * i + 1] = h1;
    g_xlo[2 * i]     = l0;  g_xlo[2 * i + 1] = l1;
}

__global__ void prep_w_kernel(const float* __restrict__ W1) {
    int idx = blockIdx.x * blockDim.x + threadIdx.x;
    if (idx >= D1 * (FIN / 2)) return;
    int n = idx >> 8;
    int kp = idx & 255;
    float a = W1[(size_t)(2 * kp) * D1 + n];
    float b = W1[(size_t)(2 * kp + 1) * D1 + n];
    uint32_t hi, lo;
    split2(a, b, hi, lo);
    g_w1t_hi[idx] = hi;
    g_w1t_lo[idx] = lo;
}

// ---------------- tensor-core GEMM1 + fused alpha1 ----------------------------
#define MMA_BF16(c, a0, a1, a2, a3, b0, b1)                                    \
    asm volatile(                                                              \
        "mma.sync.aligned.m16n8k16.row.col.f32.bf16.bf16.f32 "                 \
        "{%0,%1,%2,%3}, {%4,%5,%6,%7}, {%8,%9}, {%0,%1,%2,%3};\n"              \
        : "+f"(c[0]), "+f"(c[1]), "+f"(c[2]), "+f"(c[3])                       \
        : "r"(a0), "r"(a1), "r"(a2), "r"(a3), "r"(b0), "r"(b1))

__device__ __forceinline__ void ldm4(uint32_t* r, uint32_t saddr) {
    asm volatile("ldmatrix.sync.aligned.m8n8.x4.shared.b16 {%0,%1,%2,%3}, [%4];"
                 : "=r"(r[0]), "=r"(r[1]), "=r"(r[2]), "=r"(r[3]) : "r"(saddr));
}

__global__ void __launch_bounds__(256, 2) sgemm1_tc_kernel(const float* __restrict__ a_src1,
                                                           const float* __restrict__ a_dst1) {
    __shared__ uint32_t As_hi[2][128 * 8];
    __shared__ uint32_t As_lo[2][128 * 8];
    __shared__ uint32_t Bs_hi[2][128 * 8];
    __shared__ uint32_t Bs_lo[2][128 * 8];

    const int t = threadIdx.x, lane = t & 31, wid = t >> 5;
    const int warpM = wid >> 1, warpN = wid & 1;
    const int rowBase = blockIdx.y * 128, colBase = blockIdx.x * 128;

    const int lrow  = t >> 1;
    const int lhalf = t & 1;
    const int arow_g = rowBase + lrow;
    const bool avalid = arow_g < NN;
    const size_t a_base = (size_t)(avalid ? arow_g : 0) * (FIN / 2) + lhalf * 4;
    const size_t b_base = (size_t)(colBase + lrow) * (FIN / 2) + lhalf * 4;
    const int s_off = lrow * 8 + ((lhalf * 4) ^ (lrow & 4));

    const int lr = lane & 15, kq = lane >> 4;
    uint32_t off_a[2], off_b[4];
#pragma unroll
    for (int mt = 0; mt < 2; mt++) {
        int r = warpM * 32 + mt * 16 + lr;
        off_a[mt] = (uint32_t)(r * 8 + ((kq * 4) ^ (r & 4))) * 4u;
    }
#pragma unroll
    for (int np = 0; np < 4; np++) {
        int r = warpN * 64 + np * 16 + lr;
        off_b[np] = (uint32_t)(r * 8 + ((kq * 4) ^ (r & 4))) * 4u;
    }
    uint32_t baseAh[2], baseAl[2], baseBh[2], baseBl[2];
#pragma unroll
    for (int b = 0; b < 2; b++) {
        baseAh[b] = (uint32_t)__cvta_generic_to_shared(&As_hi[b][0]);
        baseAl[b] = (uint32_t)__cvta_generic_to_shared(&As_lo[b][0]);
        baseBh[b] = (uint32_t)__cvta_generic_to_shared(&Bs_hi[b][0]);
        baseBl[b] = (uint32_t)__cvta_generic_to_shared(&Bs_lo[b][0]);
    }

    float acc[2][8][4];
#pragma unroll
    for (int mt = 0; mt < 2; mt++)
#pragma unroll
        for (int nt = 0; nt < 8; nt++)
#pragma unroll
            for (int q = 0; q < 4; q++) acc[mt][nt][q] = 0.f;

    const uint4 z4 = make_uint4(0, 0, 0, 0);
    uint4 ra_h, ra_l, rb_h, rb_l;

    ra_h = avalid ? *(const uint4*)&g_xhi[a_base] : z4;
    ra_l = avalid ? *(const uint4*)&g_xlo[a_base] : z4;
    rb_h = *(const uint4*)&g_w1t_hi[b_base];
    rb_l = *(const uint4*)&g_w1t_lo[b_base];
    *(uint4*)&As_hi[0][s_off] = ra_h;
    *(uint4*)&As_lo[0][s_off] = ra_l;
    *(uint4*)&Bs_hi[0][s_off] = rb_h;
    *(uint4*)&Bs_lo[0][s_off] = rb_l;
    __syncthreads();

    const int NSTAGE = FIN / 16;    // 32
    for (int ks = 0; ks < NSTAGE; ks++) {
        const int cur = ks & 1;
        if (ks + 1 < NSTAGE) {
            size_t off = (size_t)(ks + 1) * 8;
            ra_h = avalid ? *(const uint4*)&g_xhi[a_base + off] : z4;
            ra_l = avalid ? *(const uint4*)&g_xlo[a_base + off] : z4;
            rb_h = *(const uint4*)&g_w1t_hi[b_base + off];
            rb_l = *(const uint4*)&g_w1t_lo[b_base + off];
        }

        uint32_t afh[2][4], afl[2][4];
        ldm4(afh[0], baseAh[cur] + off_a[0]);
        ldm4(afh[1], baseAh[cur] + off_a[1]);
        ldm4(afl[0], baseAl[cur] + off_a[0]);
        ldm4(afl[1], baseAl[cur] + off_a[1]);

#pragma unroll
        for (int np = 0; np < 4; np++) {
            uint32_t bh[4], bl[4];
            ldm4(bh, baseBh[cur] + off_b[np]);
            ldm4(bl, baseBl[cur] + off_b[np]);
#pragma unroll
            for (int mt = 0; mt < 2; mt++) {
                MMA_BF16(acc[mt][2 * np],     afh[mt][0], afh[mt][1], afh[mt][2], afh[mt][3], bh[0], bh[2]);
                MMA_BF16(acc[mt][2 * np],     afh[mt][0], afh[mt][1], afh[mt][2], afh[mt][3], bl[0], bl[2]);
                MMA_BF16(acc[mt][2 * np],     afl[mt][0], afl[mt][1], afl[mt][2], afl[mt][3], bh[0], bh[2]);
                MMA_BF16(acc[mt][2 * np + 1], afh[mt][0], afh[mt][1], afh[mt][2], afh[mt][3], bh[1], bh[3]);
                MMA_BF16(acc[mt][2 * np + 1], afh[mt][0], afh[mt][1], afh[mt][2], afh[mt][3], bl[1], bl[3]);
                MMA_BF16(acc[mt][2 * np + 1], afl[mt][0], afl[mt][1], afl[mt][2], afl[mt][3], bh[1], bh[3]);
            }
        }
        if (ks + 1 < NSTAGE) {
            const int nxt = 1 - cur;
            *(uint4*)&As_hi[nxt][s_off] = ra_h;
            *(uint4*)&As_lo[nxt][s_off] = ra_l;
            *(uint4*)&Bs_hi[nxt][s_off] = rb_h;
            *(uint4*)&Bs_lo[nxt][s_off] = rb_l;
            __syncthreads();
        }
    }

    // ---- epilogue: stage a-vectors in smem, then store h1 + fused alpha1 -----
    __syncthreads();
    float* avec = (float*)&As_hi[0][0];          // [0:128) a_src, [128:256) a_dst
    if (t < 128) {
        avec[t]       = __ldg(&a_src1[colBase + t]);
        avec[128 + t] = __ldg(&a_dst1[colBase + t]);
    }
    __syncthreads();

#pragma unroll
    for (int mt = 0; mt < 2; mt++) {
        const int r0 = rowBase + warpM * 32 + mt * 16 + (lane >> 2);
        const int r1 = r0 + 8;
#pragma unroll
        for (int nt = 0; nt < 8; nt++) {
            const int c = colBase + warpN * 64 + nt * 8 + (lane & 3) * 2;
            if (r0 < NN) *(float2*)&g_h1[(size_t)r0 * D1 + c] = make_float2(acc[mt][nt][0], acc[mt][nt][1]);
            if (r1 < NN) *(float2*)&g_h1[(size_t)r1 * D1 + c] = make_float2(acc[mt][nt][2], acc[mt][nt][3]);
        }
#pragma unroll
        for (int hl = 0; hl < 2; hl++) {
            float ps0 = 0.f, pd0 = 0.f, ps1 = 0.f, pd1 = 0.f;
#pragma unroll
            for (int ntq = 0; ntq < 4; ntq++) {
                const int nt = hl * 4 + ntq;
                const int cl = warpN * 64 + nt * 8 + (lane & 3) * 2;   // local col
                float av0 = avec[cl],       av1 = avec[cl + 1];
                float dv0 = avec[128 + cl], dv1 = avec[128 + cl + 1];
                ps0 += acc[mt][nt][0] * av0 + acc[mt][nt][1] * av1;
                pd0 += acc[mt][nt][0] * dv0 + acc[mt][nt][1] * dv1;
                ps1 += acc[mt][nt][2] * av0 + acc[mt][nt][3] * av1;
                pd1 += acc[mt][nt][2] * dv0 + acc[mt][nt][3] * dv1;
            }
#pragma unroll
            for (int off = 1; off < 4; off <<= 1) {
                ps0 += __shfl_xor_sync(0xffffffffu, ps0, off);
                pd0 += __shfl_xor_sync(0xffffffffu, pd0, off);
                ps1 += __shfl_xor_sync(0xffffffffu, ps1, off);
                pd1 += __shfl_xor_sync(0xffffffffu, pd1, off);
            }
            if ((lane & 3) == 0) {
                const int hg = (colBase >> 5) + warpN * 2 + hl;
                if (r0 < NN) { g_as1[r0 * H1 + hg] = ps0; g_ad1[r0 * H1 + hg] = pd0; }
                if (r1 < NN) { g_as1[r1 * H1 + hg] = ps1; g_ad1[r1 * H1 + hg] = pd1; }
            }
        }
    }
}

// ---------------- CSR build ---------------------------------------------------
__global__ void zero_deg_kernel() {
    int i = blockIdx.x * blockDim.x + threadIdx.x;
    if (i < NN) g_deg[i] = 0;
}

__global__ void hist_kernel(const int* __restrict__ ei) {
    int i = blockIdx.x * blockDim.x + threadIdx.x;
    if (i >= E2) return;
    int d = (i < EE) ? __ldg(&ei[EE + i]) : (i - EE);
    atomicAdd(&g_deg[d], 1);
}

__global__ void scan_block_kernel() {
    __shared__ int sh[1024];
    int tid = threadIdx.x;
    int i = blockIdx.x * 1024 + tid;
    int v = (i < NN) ? g_deg[i] : 0;
    sh[tid] = v;
    __syncthreads();
#pragma unroll
    for (int off = 1; off < 1024; off <<= 1) {
        int t = (tid >= off) ? sh[tid - off] : 0;
        __syncthreads();
        sh[tid] += t;
        __syncthreads();
    }
    if (i < NN) g_incl[i] = sh[tid];
    if (tid == 1023) g_parts[blockIdx.x] = sh[tid];
}

__global__ void scan_parts_kernel(int nb) {
    __shared__ int sh[64];
    int tid = threadIdx.x;
    int v = (tid < nb) ? g_parts[tid] : 0;
    sh[tid] = v;
    __syncthreads();
#pragma unroll
    for (int off = 1; off < 64; off <<= 1) {
        int t = (tid >= off) ? sh[tid - off] : 0;
        __syncthreads();
        sh[tid] += t;
        __syncthreads();
    }
    if (tid < nb) g_parts_ex[tid] = sh[tid] - v;
}

__global__ void finalize_scan_kernel() {
    int i = blockIdx.x * blockDim.x + threadIdx.x;
    if (i >= NN) return;
    int start = g_incl[i] - g_deg[i] + g_parts_ex[i >> 10];
    g_starts[i] = start;
    g_cursor[i] = start;
}

__global__ void fill_kernel(const int* __restrict__ ei) {
    int i = blockIdx.x * blockDim.x + threadIdx.x;
    if (i >= E2) return;
    int s, d;
    if (i < EE) { s = __ldg(&ei[i]); d = __ldg(&ei[EE + i]); }
    else        { s = i - EE; d = s; }
    int p = atomicAdd(&g_cursor[d], 1);
    g_ssrc[p] = s;
}

// ---------------- edge weights: warp per node, all 8 heads --------------------
__global__ void edgew_kernel() {
    int n = (blockIdx.x * blockDim.x + threadIdx.x) >> 5;
    int lane = threadIdx.x & 31;
    if (n >= NN) return;
    int st = g_starts[n];
    int d  = g_deg[n];

    // destination logits for this node (one 32B row)
    float4 ad0 = *(const float4*)&g_ad1[n * H1];
    float4 ad1 = *(const float4*)&g_ad1[n * H1 + 4];

    float den[H1];
#pragma unroll
    for (int h = 0; h < H1; h++) den[h] = 0.f;

    for (int j = lane; j < d; j += 32) {
        int s = __ldg(&g_ssrc[st + j]);
        const float4* ap = (const float4*)&g_as1[s * H1];
        float4 a0 = __ldg(ap), a1 = __ldg(ap + 1);     // one 32B sector
        float e[H1];
        e[0] = a0.x + ad0.x;  e[1] = a0.y + ad0.y;
        e[2] = a0.z + ad0.z;  e[3] = a0.w + ad0.w;
        e[4] = a1.x + ad1.x;  e[5] = a1.y + ad1.y;
        e[6] = a1.z + ad1.z;  e[7] = a1.w + ad1.w;
#pragma unroll
        for (int h = 0; h < H1; h++) {
            float ee = fmaxf(e[h], 0.2f * e[h]);
            float x = __expf(ee);
            g_wbuf[(size_t)h * E2 + st + j] = x;       // coalesced per plane
            den[h] += x;
        }
    }
#pragma unroll
    for (int h = 0; h < H1; h++) {
#pragma unroll
        for (int off = 16; off > 0; off >>= 1)
            den[h] += __shfl_xor_sync(0xffffffffu, den[h], off);
    }
    if (lane == 0) {
#pragma unroll
        for (int h = 0; h < H1; h++)
            g_deninv[n * H1 + h] = 1.f / (den[h] + 1e-16f);
    }
}

// ---------------- layer1 aggregation (warp per node*head, gather only) --------
__global__ void agg1_kernel(const float* __restrict__ b1) {
    int gw = (blockIdx.x * blockDim.x + threadIdx.x) >> 5;
    int lane = threadIdx.x & 31;
    int n = gw >> 3;                 // node
    int h = gw & 7;                  // head
    if (n >= NN) return;
    int st = g_starts[n];
    int d  = g_deg[n];

    float inv = __ldg(&g_deninv[n * H1 + h]);
    const float* wplane = &g_wbuf[(size_t)h * E2];

    float a0 = 0.f;
#pragma unroll 8
    for (int j = 0; j < d; j++) {
        int s = __ldg(&g_ssrc[st + j]);
        float w = __ldg(&wplane[st + j]) * inv;
        a0 = fmaf(__ldg(&g_h1[(size_t)s * D1 + h * 32 + lane]), w, a0);
    }

    float v = a0 + __ldg(&b1[h * 32 + lane]);
    v = (v > 0.f) ? v : expm1f(v);
    g_hout1[(size_t)n * D1 + h * 32 + lane] = v;
}

// ---------------- layer2 linear + alpha2 --------------------------------------
__global__ void layer2_linear_kernel(const float* __restrict__ W2,
                                     const float* __restrict__ a_src2,
                                     const float* __restrict__ a_dst2) {
    __shared__ float Ws[D1 * CLS + 64];
    __shared__ float as_sh[CLS], ad_sh[CLS];
    int tid = threadIdx.x;
    for (int i = tid; i < D1 * CLS + 64; i += blockDim.x)
        Ws[i] = (i < D1 * CLS) ? W2[i] : 0.f;
    if (tid < CLS) { as_sh[tid] = a_src2[tid]; ad_sh[tid] = a_dst2[tid]; }
    __syncthreads();

    int lane = tid & 31;
    int warpsPerBlock = blockDim.x >> 5;
    int gw = blockIdx.x * warpsPerBlock + (tid >> 5);
    int stride = gridDim.x * warpsPerBlock;

    for (int n = gw; n < NN; n += stride) {
        const float* xp = &g_hout1[(size_t)n * D1];
        float acc0a = 0.f, acc0b = 0.f, acc1a = 0.f, acc1b = 0.f;
#pragma unroll
        for (int kb = 0; kb < D1 / 32; kb++) {
            float xv = xp[kb * 32 + lane];
#pragma unroll
            for (int j = 0; j < 32; j += 2) {
                float xj0 = __shfl_sync(0xffffffffu, xv, j);
                float xj1 = __shfl_sync(0xffffffffu, xv, j + 1);
                int k0 = kb * 32 + j;
                acc0a = fmaf(xj0, Ws[k0 * CLS + lane], acc0a);
                acc1a = fmaf(xj0, Ws[k0 * CLS + 32 + lane], acc1a);
                acc0b = fmaf(xj1, Ws[(k0 + 1) * CLS + lane], acc0b);
                acc1b = fmaf(xj1, Ws[(k0 + 1) * CLS + 32 + lane], acc1b);
            }
        }
        float v0 = acc0a + acc0b;
        float v1 = acc1a + acc1b;
        g_h2lin[(size_t)n * CLS + lane] = v0;
        if (lane < CLS - 32) g_h2lin[(size_t)n * CLS + 32 + lane] = v1;
        float ps = v0 * as_sh[lane] + ((lane < CLS - 32) ? v1 * as_sh[32 + lane] : 0.f);
        float pd = v0 * ad_sh[lane] + ((lane < CLS - 32) ? v1 * ad_sh[32 + lane] : 0.f);
#pragma unroll
        for (int off = 16; off > 0; off >>= 1) {
            ps += __shfl_xor_sync(0xffffffffu, ps, off);
            pd += __shfl_xor_sync(0xffffffffu, pd, off);
        }
        if (lane == 0) { g_as2[n] = ps; g_ad2[n] = pd; }
    }
}

// ---------------- layer2 aggregation + log_softmax ----------------------------
__global__ void agg2_kernel(const float* __restrict__ b2, float* __restrict__ out) {
    int n = (blockIdx.x * blockDim.x + threadIdx.x) >> 5;
    int lane = threadIdx.x & 31;
    if (n >= NN) return;
    int st = g_starts[n];
    int d  = g_deg[n];
    float adn = g_ad2[n];

    float den = 0.f;
    for (int j = lane; j < d; j += 32) {
        int s = __ldg(&g_ssrc[st + j]);
        float e = __ldg(&g_as2[s]) + adn;
        e = fmaxf(e, 0.2f * e);
        float ex = __expf(e);
        g_wbuf2[st + j] = ex;
        den += ex;
    }
#pragma unroll
    for (int off = 16; off > 0; off >>= 1)
        den += __shfl_xor_sync(0xffffffffu, den, off);
    float inv = 1.f / (den + 1e-16f);

    float acc0 = 0.f, acc1 = 0.f;
#pragma unroll 4
    for (int j = 0; j < d; j++) {
        int s = __ldg(&g_ssrc[st + j]);
        float w = g_wbuf2[st + j] * inv;
        const float* hp = &g_h2lin[(size_t)s * CLS];
        acc0 = fmaf(__ldg(&hp[lane]), w, acc0);
        if (lane < CLS - 32) acc1 = fmaf(__ldg(&hp[32 + lane]), w, acc1);
    }
    float v0 = acc0 + __ldg(&b2[lane]);
    float v1 = (lane < CLS - 32) ? (acc1 + __ldg(&b2[32 + lane])) : -CUDART_INF_F;

    float m = fmaxf(v0, v1);
#pragma unroll
    for (int off = 16; off > 0; off >>= 1)
        m = fmaxf(m, __shfl_xor_sync(0xffffffffu, m, off));
    float s0 = __expf(v0 - m) + ((lane < CLS - 32) ? __expf(v1 - m) : 0.f);
#pragma unroll
    for (int off = 16; off > 0; off >>= 1)
        s0 += __shfl_xor_sync(0xffffffffu, s0, off);
    float lse = m + logf(s0);

    out[(size_t)n * CLS + lane] = v0 - lse;
    if (lane < CLS - 32) out[(size_t)n * CLS + 32 + lane] = v1 - lse;
}

// ---------------- launch ------------------------------------------------------
extern "C" void kernel_launch(void* const* d_in, const int* in_sizes, int n_in,
                              void* d_out, int out_size) {
    const float* x      = (const float*)d_in[0];
    const int*   ei     = (const int*)d_in[1];
    const float* W1     = (const float*)d_in[2];
    const float* a_src1 = (const float*)d_in[3];
    const float* a_dst1 = (const float*)d_in[4];
    const float* b1     = (const float*)d_in[5];
    const float* W2     = (const float*)d_in[6];
    const float* a_src2 = (const float*)d_in[7];
    const float* a_dst2 = (const float*)d_in[8];
    const float* b2     = (const float*)d_in[9];
    float* out = (float*)d_out;

    const int nb_scan = (NN + 1023) / 1024;   // 49

    // prep, then GEMM at launch slot 4 (ncu capture window)
    prep_x_kernel<<<(NN * FIN / 4 + 255) / 256, 256>>>(x);
    prep_w_kernel<<<(D1 * (FIN / 2) + 255) / 256, 256>>>(W1);
    zero_deg_kernel<<<(NN + 255) / 256, 256>>>();
    sgemm1_tc_kernel<<<dim3(2, (NN + 127) / 128), 256>>>(a_src1, a_dst1);

    // CSR build chain
    hist_kernel<<<(E2 + 255) / 256, 256>>>(ei);
    scan_block_kernel<<<nb_scan, 1024>>>();
    scan_parts_kernel<<<1, 64>>>(nb_scan);
    finalize_scan_kernel<<<(NN + 255) / 256, 256>>>();
    fill_kernel<<<(E2 + 255) / 256, 256>>>(ei);

    // layer 1: edge weights (all heads), then gather-only aggregation
    edgew_kernel<<<(NN * 32 + 255) / 256, 256>>>();
    agg1_kernel<<<((size_t)NN * 8 * 32 + 255) / 256, 256>>>(b1);

    // layer 2
    layer2_linear_kernel<<<592, 256>>>(W2, a_src2, a_dst2);
    agg2_kernel<<<(NN * 32 + 255) / 256, 256>>>(b2, out);
}

// round 10
// speedup vs baseline: 1.0491x; 1.0491x over previous
#include <cuda_runtime.h>
#include <cuda_bf16.h>
#include <math_constants.h>
#include <cstdint>

// Problem constants (fixed by the dataset)
#define NN   50000
#define EE   800000
#define E2   (EE + NN)      // edges + self loops = 850000
#define FIN  512
#define H1   8
#define C1   32
#define D1   (H1 * C1)      // 256
#define CLS  40

// ---------------- scratch (static device globals; no runtime alloc) ----------
__device__ float g_h1[NN * D1];          // layer1 linear output [N,256]
__device__ float g_as1[NN * H1];
__device__ float g_ad1[NN * H1];
__device__ float g_hout1[NN * D1];       // elu(agg1 + b1) [N,256]
__device__ float g_h2lin[NN * CLS];
__device__ float g_as2[NN];
__device__ float g_ad2[NN];
__device__ float g_wbuf[E2 * H1];        // per-edge exp(logit), interleaved [edge][h]
__device__ float g_wbuf2[E2];
__device__ int   g_deg[NN];
__device__ int   g_incl[NN];
__device__ int   g_starts[NN];
__device__ int   g_cursor[NN];
__device__ int   g_ssrc[E2];
__device__ int   g_parts[64];
__device__ int   g_parts_ex[64];
// bf16 split-precision operands for GEMM1
__device__ uint32_t g_xhi[NN * (FIN / 2)];
__device__ uint32_t g_xlo[NN * (FIN / 2)];
__device__ uint32_t g_w1t_hi[D1 * (FIN / 2)];
__device__ uint32_t g_w1t_lo[D1 * (FIN / 2)];

// ---------------- bf16 split helpers -----------------------------------------
__device__ __forceinline__ void split2(float x, float y, uint32_t& hi, uint32_t& lo) {
    __nv_bfloat16 hx = __float2bfloat16_rn(x);
    __nv_bfloat16 hy = __float2bfloat16_rn(y);
    float lxf = x - __bfloat162float(hx);
    float lyf = y - __bfloat162float(hy);
    __nv_bfloat162 hv; hv.x = hx; hv.y = hy;
    __nv_bfloat162 lv = __floats2bfloat162_rn(lxf, lyf);
    hi = *reinterpret_cast<uint32_t*>(&hv);
    lo = *reinterpret_cast<uint32_t*>(&lv);
}

__global__ void prep_x_kernel(const float* __restrict__ x) {
    int i = blockIdx.x * blockDim.x + threadIdx.x;
    const int NQ = NN * FIN / 4;
    if (i >= NQ) return;
    float4 v = ((const float4*)x)[i];
    uint32_t h0, l0, h1, l1;
    split2(v.x, v.y, h0, l0);
    split2(v.z, v.w, h1, l1);
    g_xhi[2 * i]     = h0;  g_xhi[2 * i + 1] = h1;
    g_xlo[2 * i]     = l0;  g_xlo[2 * i + 1] = l1;
}

__global__ void prep_w_kernel(const float* __restrict__ W1) {
    int idx = blockIdx.x * blockDim.x + threadIdx.x;
    if (idx >= D1 * (FIN / 2)) return;
    int n = idx >> 8;
    int kp = idx & 255;
    float a = W1[(size_t)(2 * kp) * D1 + n];
    float b = W1[(size_t)(2 * kp + 1) * D1 + n];
    uint32_t hi, lo;
    split2(a, b, hi, lo);
    g_w1t_hi[idx] = hi;
    g_w1t_lo[idx] = lo;
}

// ---------------- tensor-core GEMM1 (R5 config, no fused epilogue) ------------
#define MMA_BF16(c, a0, a1, a2, a3, b0, b1)                                    \
    asm volatile(                                                              \
        "mma.sync.aligned.m16n8k16.row.col.f32.bf16.bf16.f32 "                 \
        "{%0,%1,%2,%3}, {%4,%5,%6,%7}, {%8,%9}, {%0,%1,%2,%3};\n"              \
        : "+f"(c[0]), "+f"(c[1]), "+f"(c[2]), "+f"(c[3])                       \
        : "r"(a0), "r"(a1), "r"(a2), "r"(a3), "r"(b0), "r"(b1))

__device__ __forceinline__ void ldm4(uint32_t* r, uint32_t saddr) {
    asm volatile("ldmatrix.sync.aligned.m8n8.x4.shared.b16 {%0,%1,%2,%3}, [%4];"
                 : "=r"(r[0]), "=r"(r[1]), "=r"(r[2]), "=r"(r[3]) : "r"(saddr));
}

__global__ void __launch_bounds__(256, 2) sgemm1_tc_kernel() {
    __shared__ uint32_t As_hi[2][128 * 8];
    __shared__ uint32_t As_lo[2][128 * 8];
    __shared__ uint32_t Bs_hi[2][128 * 8];
    __shared__ uint32_t Bs_lo[2][128 * 8];

    const int t = threadIdx.x, lane = t & 31, wid = t >> 5;
    const int warpM = wid >> 1, warpN = wid & 1;
    const int rowBase = blockIdx.y * 128, colBase = blockIdx.x * 128;

    const int lrow  = t >> 1;
    const int lhalf = t & 1;
    const int arow_g = rowBase + lrow;
    const bool avalid = arow_g < NN;
    const size_t a_base = (size_t)(avalid ? arow_g : 0) * (FIN / 2) + lhalf * 4;
    const size_t b_base = (size_t)(colBase + lrow) * (FIN / 2) + lhalf * 4;
    const int s_off = lrow * 8 + ((lhalf * 4) ^ (lrow & 4));

    const int lr = lane & 15, kq = lane >> 4;
    uint32_t off_a[2], off_b[4];
#pragma unroll
    for (int mt = 0; mt < 2; mt++) {
        int r = warpM * 32 + mt * 16 + lr;
        off_a[mt] = (uint32_t)(r * 8 + ((kq * 4) ^ (r & 4))) * 4u;
    }
#pragma unroll
    for (int np = 0; np < 4; np++) {
        int r = warpN * 64 + np * 16 + lr;
        off_b[np] = (uint32_t)(r * 8 + ((kq * 4) ^ (r & 4))) * 4u;
    }
    uint32_t baseAh[2], baseAl[2], baseBh[2], baseBl[2];
#pragma unroll
    for (int b = 0; b < 2; b++) {
        baseAh[b] = (uint32_t)__cvta_generic_to_shared(&As_hi[b][0]);
        baseAl[b] = (uint32_t)__cvta_generic_to_shared(&As_lo[b][0]);
        baseBh[b] = (uint32_t)__cvta_generic_to_shared(&Bs_hi[b][0]);
        baseBl[b] = (uint32_t)__cvta_generic_to_shared(&Bs_lo[b][0]);
    }

    float acc[2][8][4];
#pragma unroll
    for (int mt = 0; mt < 2; mt++)
#pragma unroll
        for (int nt = 0; nt < 8; nt++)
#pragma unroll
            for (int q = 0; q < 4; q++) acc[mt][nt][q] = 0.f;

    const uint4 z4 = make_uint4(0, 0, 0, 0);
    uint4 ra_h, ra_l, rb_h, rb_l;

    ra_h = avalid ? *(const uint4*)&g_xhi[a_base] : z4;
    ra_l = avalid ? *(const uint4*)&g_xlo[a_base] : z4;
    rb_h = *(const uint4*)&g_w1t_hi[b_base];
    rb_l = *(const uint4*)&g_w1t_lo[b_base];
    *(uint4*)&As_hi[0][s_off] = ra_h;
    *(uint4*)&As_lo[0][s_off] = ra_l;
    *(uint4*)&Bs_hi[0][s_off] = rb_h;
    *(uint4*)&Bs_lo[0][s_off] = rb_l;
    __syncthreads();

    const int NSTAGE = FIN / 16;    // 32
    for (int ks = 0; ks < NSTAGE; ks++) {
        const int cur = ks & 1;
        if (ks + 1 < NSTAGE) {
            size_t off = (size_t)(ks + 1) * 8;
            ra_h = avalid ? *(const uint4*)&g_xhi[a_base + off] : z4;
            ra_l = avalid ? *(const uint4*)&g_xlo[a_base + off] : z4;
            rb_h = *(const uint4*)&g_w1t_hi[b_base + off];
            rb_l = *(const uint4*)&g_w1t_lo[b_base + off];
        }

        uint32_t afh[2][4], afl[2][4];
        ldm4(afh[0], baseAh[cur] + off_a[0]);
        ldm4(afh[1], baseAh[cur] + off_a[1]);
        ldm4(afl[0], baseAl[cur] + off_a[0]);
        ldm4(afl[1], baseAl[cur] + off_a[1]);

#pragma unroll
        for (int np = 0; np < 4; np++) {
            uint32_t bh[4], bl[4];
            ldm4(bh, baseBh[cur] + off_b[np]);
            ldm4(bl, baseBl[cur] + off_b[np]);
#pragma unroll
            for (int mt = 0; mt < 2; mt++) {
                MMA_BF16(acc[mt][2 * np],     afh[mt][0], afh[mt][1], afh[mt][2], afh[mt][3], bh[0], bh[2]);
                MMA_BF16(acc[mt][2 * np],     afh[mt][0], afh[mt][1], afh[mt][2], afh[mt][3], bl[0], bl[2]);
                MMA_BF16(acc[mt][2 * np],     afl[mt][0], afl[mt][1], afl[mt][2], afl[mt][3], bh[0], bh[2]);
                MMA_BF16(acc[mt][2 * np + 1], afh[mt][0], afh[mt][1], afh[mt][2], afh[mt][3], bh[1], bh[3]);
                MMA_BF16(acc[mt][2 * np + 1], afh[mt][0], afh[mt][1], afh[mt][2], afh[mt][3], bl[1], bl[3]);
                MMA_BF16(acc[mt][2 * np + 1], afl[mt][0], afl[mt][1], afl[mt][2], afl[mt][3], bh[1], bh[3]);
            }
        }
        if (ks + 1 < NSTAGE) {
            const int nxt = 1 - cur;
            *(uint4*)&As_hi[nxt][s_off] = ra_h;
            *(uint4*)&As_lo[nxt][s_off] = ra_l;
            *(uint4*)&Bs_hi[nxt][s_off] = rb_h;
            *(uint4*)&Bs_lo[nxt][s_off] = rb_l;
            __syncthreads();
        }
    }

#pragma unroll
    for (int mt = 0; mt < 2; mt++) {
        const int r = rowBase + warpM * 32 + mt * 16 + (lane >> 2);
#pragma unroll
        for (int nt = 0; nt < 8; nt++) {
            const int c = colBase + warpN * 64 + nt * 8 + (lane & 3) * 2;
            if (r < NN) {
                float2 v = make_float2(acc[mt][nt][0], acc[mt][nt][1]);
                *(float2*)&g_h1[(size_t)r * D1 + c] = v;
            }
            if (r + 8 < NN) {
                float2 v = make_float2(acc[mt][nt][2], acc[mt][nt][3]);
                *(float2*)&g_h1[(size_t)(r + 8) * D1 + c] = v;
            }
        }
    }
}

// ---------------- alpha1: per-node attention logits (warp per node) ----------
__global__ void alpha1_kernel(const float* __restrict__ a_src, const float* __restrict__ a_dst) {
    int gw = (blockIdx.x * blockDim.x + threadIdx.x) >> 5;
    int lane = threadIdx.x & 31;
    if (gw >= NN) return;
    const float* hp = &g_h1[(size_t)gw * D1];
#pragma unroll
    for (int h = 0; h < H1; h++) {
        float v = hp[h * 32 + lane];
        float s1 = v * __ldg(&a_src[h * 32 + lane]);
        float s2 = v * __ldg(&a_dst[h * 32 + lane]);
#pragma unroll
        for (int off = 16; off > 0; off >>= 1) {
            s1 += __shfl_xor_sync(0xffffffffu, s1, off);
            s2 += __shfl_xor_sync(0xffffffffu, s2, off);
        }
        if (lane == 0) {
            g_as1[gw * H1 + h] = s1;
            g_ad1[gw * H1 + h] = s2;
        }
    }
}

// ---------------- CSR build ---------------------------------------------------
__global__ void zero_deg_kernel() {
    int i = blockIdx.x * blockDim.x + threadIdx.x;
    if (i < NN) g_deg[i] = 0;
}

__global__ void hist_kernel(const int* __restrict__ ei) {
    int i = blockIdx.x * blockDim.x + threadIdx.x;
    if (i >= E2) return;
    int d = (i < EE) ? __ldg(&ei[EE + i]) : (i - EE);
    atomicAdd(&g_deg[d], 1);
}

__global__ void scan_block_kernel() {
    __shared__ int sh[1024];
    int tid = threadIdx.x;
    int i = blockIdx.x * 1024 + tid;
    int v = (i < NN) ? g_deg[i] : 0;
    sh[tid] = v;
    __syncthreads();
#pragma unroll
    for (int off = 1; off < 1024; off <<= 1) {
        int t = (tid >= off) ? sh[tid - off] : 0;
        __syncthreads();
        sh[tid] += t;
        __syncthreads();
    }
    if (i < NN) g_incl[i] = sh[tid];
    if (tid == 1023) g_parts[blockIdx.x] = sh[tid];
}

__global__ void scan_parts_kernel(int nb) {
    __shared__ int sh[64];
    int tid = threadIdx.x;
    int v = (tid < nb) ? g_parts[tid] : 0;
    sh[tid] = v;
    __syncthreads();
#pragma unroll
    for (int off = 1; off < 64; off <<= 1) {
        int t = (tid >= off) ? sh[tid - off] : 0;
        __syncthreads();
        sh[tid] += t;
        __syncthreads();
    }
    if (tid < nb) g_parts_ex[tid] = sh[tid] - v;
}

__global__ void finalize_scan_kernel() {
    int i = blockIdx.x * blockDim.x + threadIdx.x;
    if (i >= NN) return;
    int start = g_incl[i] - g_deg[i] + g_parts_ex[i >> 10];
    g_starts[i] = start;
    g_cursor[i] = start;
}

__global__ void fill_kernel(const int* __restrict__ ei) {
    int i = blockIdx.x * blockDim.x + threadIdx.x;
    if (i >= E2) return;
    int s, d;
    if (i < EE) { s = __ldg(&ei[i]); d = __ldg(&ei[EE + i]); }
    else        { s = i - EE; d = s; }
    int p = atomicAdd(&g_cursor[d], 1);
    g_ssrc[p] = s;
}

// ---------------- layer1 aggregation (R3 form: warp per dst node, all heads) --
__global__ void agg1_kernel(const float* __restrict__ b1) {
    int n = (blockIdx.x * blockDim.x + threadIdx.x) >> 5;
    int lane = threadIdx.x & 31;
    if (n >= NN) return;
    int st = g_starts[n];
    int d  = g_deg[n];

    float adh[H1];
#pragma unroll
    for (int h = 0; h < H1; h++) adh[h] = g_ad1[n * H1 + h];

    // pass A: per-edge exp for all heads + denominators (coalesced 1KB/warp writes)
    float den[H1];
#pragma unroll
    for (int h = 0; h < H1; h++) den[h] = 0.f;
    for (int j = lane; j < d; j += 32) {
        int s = __ldg(&g_ssrc[st + j]);
        float* wp = &g_wbuf[(size_t)(st + j) * H1];
        const float* asp = &g_as1[s * H1];
#pragma unroll
        for (int h = 0; h < H1; h++) {
            float e = __ldg(&asp[h]) + adh[h];
            e = fmaxf(e, 0.2f * e);
            float ex = __expf(e);
            wp[h] = ex;
            den[h] += ex;
        }
    }
#pragma unroll
    for (int h = 0; h < H1; h++) {
#pragma unroll
        for (int off = 16; off > 0; off >>= 1)
            den[h] += __shfl_xor_sync(0xffffffffu, den[h], off);
    }
    float inv[H1];
#pragma unroll
    for (int h = 0; h < H1; h++) inv[h] = 1.f / (den[h] + 1e-16f);

    // pass B: weighted gather accumulate (whole warp per edge, lane = channel)
    float acc[H1];
#pragma unroll
    for (int h = 0; h < H1; h++) acc[h] = 0.f;
#pragma unroll 4
    for (int j = 0; j < d; j++) {
        int s = __ldg(&g_ssrc[st + j]);
        const float* wp = &g_wbuf[(size_t)(st + j) * H1];
        const float* hp = &g_h1[(size_t)s * D1];
#pragma unroll
        for (int h = 0; h < H1; h++) {
            float w = wp[h] * inv[h];
            acc[h] = fmaf(__ldg(&hp[h * 32 + lane]), w, acc[h]);
        }
    }

#pragma unroll
    for (int h = 0; h < H1; h++) {
        float v = acc[h] + __ldg(&b1[h * 32 + lane]);
        v = (v > 0.f) ? v : expm1f(v);
        g_hout1[(size_t)n * D1 + h * 32 + lane] = v;
    }
}

// ---------------- layer2 linear + alpha2 --------------------------------------
__global__ void layer2_linear_kernel(const float* __restrict__ W2,
                                     const float* __restrict__ a_src2,
                                     const float* __restrict__ a_dst2) {
    __shared__ float Ws[D1 * CLS + 64];
    __shared__ float as_sh[CLS], ad_sh[CLS];
    int tid = threadIdx.x;
    for (int i = tid; i < D1 * CLS + 64; i += blockDim.x)
        Ws[i] = (i < D1 * CLS) ? W2[i] : 0.f;
    if (tid < CLS) { as_sh[tid] = a_src2[tid]; ad_sh[tid] = a_dst2[tid]; }
    __syncthreads();

    int lane = tid & 31;
    int warpsPerBlock = blockDim.x >> 5;
    int gw = blockIdx.x * warpsPerBlock + (tid >> 5);
    int stride = gridDim.x * warpsPerBlock;

    for (int n = gw; n < NN; n += stride) {
        const float* xp = &g_hout1[(size_t)n * D1];
        float acc0a = 0.f, acc0b = 0.f, acc1a = 0.f, acc1b = 0.f;
#pragma unroll
        for (int kb = 0; kb < D1 / 32; kb++) {
            float xv = xp[kb * 32 + lane];
#pragma unroll
            for (int j = 0; j < 32; j += 2) {
                float xj0 = __shfl_sync(0xffffffffu, xv, j);
                float xj1 = __shfl_sync(0xffffffffu, xv, j + 1);
                int k0 = kb * 32 + j;
                acc0a = fmaf(xj0, Ws[k0 * CLS + lane], acc0a);
                acc1a = fmaf(xj0, Ws[k0 * CLS + 32 + lane], acc1a);
                acc0b = fmaf(xj1, Ws[(k0 + 1) * CLS + lane], acc0b);
                acc1b = fmaf(xj1, Ws[(k0 + 1) * CLS + 32 + lane], acc1b);
            }
        }
        float v0 = acc0a + acc0b;
        float v1 = acc1a + acc1b;
        g_h2lin[(size_t)n * CLS + lane] = v0;
        if (lane < CLS - 32) g_h2lin[(size_t)n * CLS + 32 + lane] = v1;
        float ps = v0 * as_sh[lane] + ((lane < CLS - 32) ? v1 * as_sh[32 + lane] : 0.f);
        float pd = v0 * ad_sh[lane] + ((lane < CLS - 32) ? v1 * ad_sh[32 + lane] : 0.f);
#pragma unroll
        for (int off = 16; off > 0; off >>= 1) {
            ps += __shfl_xor_sync(0xffffffffu, ps, off);
            pd += __shfl_xor_sync(0xffffffffu, pd, off);
        }
        if (lane == 0) { g_as2[n] = ps; g_ad2[n] = pd; }
    }
}

// ---------------- layer2 aggregation + log_softmax ----------------------------
__global__ void agg2_kernel(const float* __restrict__ b2, float* __restrict__ out) {
    int n = (blockIdx.x * blockDim.x + threadIdx.x) >> 5;
    int lane = threadIdx.x & 31;
    if (n >= NN) return;
    int st = g_starts[n];
    int d  = g_deg[n];
    float adn = g_ad2[n];

    float den = 0.f;
    for (int j = lane; j < d; j += 32) {
        int s = __ldg(&g_ssrc[st + j]);
        float e = __ldg(&g_as2[s]) + adn;
        e = fmaxf(e, 0.2f * e);
        float ex = __expf(e);
        g_wbuf2[st + j] = ex;
        den += ex;
    }
#pragma unroll
    for (int off = 16; off > 0; off >>= 1)
        den += __shfl_xor_sync(0xffffffffu, den, off);
    float inv = 1.f / (den + 1e-16f);

    float acc0 = 0.f, acc1 = 0.f;
#pragma unroll 4
    for (int j = 0; j < d; j++) {
        int s = __ldg(&g_ssrc[st + j]);
        float w = g_wbuf2[st + j] * inv;
        const float* hp = &g_h2lin[(size_t)s * CLS];
        acc0 = fmaf(__ldg(&hp[lane]), w, acc0);
        if (lane < CLS - 32) acc1 = fmaf(__ldg(&hp[32 + lane]), w, acc1);
    }
    float v0 = acc0 + __ldg(&b2[lane]);
    float v1 = (lane < CLS - 32) ? (acc1 + __ldg(&b2[32 + lane])) : -CUDART_INF_F;

    float m = fmaxf(v0, v1);
#pragma unroll
    for (int off = 16; off > 0; off >>= 1)
        m = fmaxf(m, __shfl_xor_sync(0xffffffffu, m, off));
    float s0 = __expf(v0 - m) + ((lane < CLS - 32) ? __expf(v1 - m) : 0.f);
#pragma unroll
    for (int off = 16; off > 0; off >>= 1)
        s0 += __shfl_xor_sync(0xffffffffu, s0, off);
    float lse = m + logf(s0);

    out[(size_t)n * CLS + lane] = v0 - lse;
    if (lane < CLS - 32) out[(size_t)n * CLS + 32 + lane] = v1 - lse;
}

// ---------------- launch ------------------------------------------------------
extern "C" void kernel_launch(void* const* d_in, const int* in_sizes, int n_in,
                              void* d_out, int out_size) {
    const float* x      = (const float*)d_in[0];
    const int*   ei     = (const int*)d_in[1];
    const float* W1     = (const float*)d_in[2];
    const float* a_src1 = (const float*)d_in[3];
    const float* a_dst1 = (const float*)d_in[4];
    const float* b1     = (const float*)d_in[5];
    const float* W2     = (const float*)d_in[6];
    const float* a_src2 = (const float*)d_in[7];
    const float* a_dst2 = (const float*)d_in[8];
    const float* b2     = (const float*)d_in[9];
    float* out = (float*)d_out;

    const int nb_scan = (NN + 1023) / 1024;   // 49

    // prep, then GEMM at launch slot 4 (ncu capture window)
    prep_x_kernel<<<(NN * FIN / 4 + 255) / 256, 256>>>(x);
    prep_w_kernel<<<(D1 * (FIN / 2) + 255) / 256, 256>>>(W1);
    zero_deg_kernel<<<(NN + 255) / 256, 256>>>();
    sgemm1_tc_kernel<<<dim3(2, (NN + 127) / 128), 256>>>();

    // CSR build chain
    hist_kernel<<<(E2 + 255) / 256, 256>>>(ei);
    scan_block_kernel<<<nb_scan, 1024>>>();
    scan_parts_kernel<<<1, 64>>>(nb_scan);
    finalize_scan_kernel<<<(NN + 255) / 256, 256>>>();
    fill_kernel<<<(E2 + 255) / 256, 256>>>(ei);

    // layer 1
    alpha1_kernel<<<(NN * 32 + 255) / 256, 256>>>(a_src1, a_dst1);
    agg1_kernel<<<(NN * 32 + 255) / 256, 256>>>(b1);

    // layer 2
    layer2_linear_kernel<<<592, 256>>>(W2, a_src2, a_dst2);
    agg2_kernel<<<(NN * 32 + 255) / 256, 256>>>(b2, out);
}

// round 11
// speedup vs baseline: 1.0780x; 1.0276x over previous
#include <cuda_runtime.h>
#include <cuda_bf16.h>
#include <math_constants.h>
#include <cstdint>

// Problem constants (fixed by the dataset)
#define NN   50000
#define EE   800000
#define E2   (EE + NN)      // edges + self loops = 850000
#define FIN  512
#define H1   8
#define C1   32
#define D1   (H1 * C1)      // 256
#define CLS  40
#define CLSP 64              // padded h2lin row (256B aligned)

// ---------------- scratch (static device globals; no runtime alloc) ----------
__device__ float g_h1[NN * D1];          // layer1 linear output [N,256]
__device__ float g_as1[NN * H1];
__device__ float g_ad1[NN * H1];
__device__ float g_hout1[NN * D1];       // elu(agg1 + b1) [N,256]
__device__ float g_h2lin[NN * CLSP];     // layer2 linear output, padded rows
__device__ float g_as2[NN];
__device__ float g_ad2[NN];
__device__ float g_wbuf[E2 * H1];        // per-edge exp(logit), interleaved [edge][h]
__device__ float g_wbuf2[E2];
__device__ int   g_deg[NN];
__device__ int   g_incl[NN];
__device__ int   g_starts[NN];
__device__ int   g_cursor[NN];
__device__ int   g_ssrc[E2];
__device__ int   g_parts[64];
__device__ int   g_parts_ex[64];
// bf16 split-precision operands for GEMM1
__device__ uint32_t g_xhi[NN * (FIN / 2)];
__device__ uint32_t g_xlo[NN * (FIN / 2)];
__device__ uint32_t g_w1t_hi[D1 * (FIN / 2)];
__device__ uint32_t g_w1t_lo[D1 * (FIN / 2)];

// ---------------- bf16 split helpers -----------------------------------------
__device__ __forceinline__ void split2(float x, float y, uint32_t& hi, uint32_t& lo) {
    __nv_bfloat16 hx = __float2bfloat16_rn(x);
    __nv_bfloat16 hy = __float2bfloat16_rn(y);
    float lxf = x - __bfloat162float(hx);
    float lyf = y - __bfloat162float(hy);
    __nv_bfloat162 hv; hv.x = hx; hv.y = hy;
    __nv_bfloat162 lv = __floats2bfloat162_rn(lxf, lyf);
    hi = *reinterpret_cast<uint32_t*>(&hv);
    lo = *reinterpret_cast<uint32_t*>(&lv);
}

__global__ void prep_x_kernel(const float* __restrict__ x) {
    int i = blockIdx.x * blockDim.x + threadIdx.x;
    const int NQ = NN * FIN / 4;
    if (i >= NQ) return;
    float4 v = ((const float4*)x)[i];
    uint32_t h0, l0, h1, l1;
    split2(v.x, v.y, h0, l0);
    split2(v.z, v.w, h1, l1);
    g_xhi[2 * i]     = h0;  g_xhi[2 * i + 1] = h1;
    g_xlo[2 * i]     = l0;  g_xlo[2 * i + 1] = l1;
}

__global__ void prep_w_kernel(const float* __restrict__ W1) {
    int idx = blockIdx.x * blockDim.x + threadIdx.x;
    if (idx >= D1 * (FIN / 2)) return;
    int n = idx >> 8;
    int kp = idx & 255;
    float a = W1[(size_t)(2 * kp) * D1 + n];
    float b = W1[(size_t)(2 * kp + 1) * D1 + n];
    uint32_t hi, lo;
    split2(a, b, hi, lo);
    g_w1t_hi[idx] = hi;
    g_w1t_lo[idx] = lo;
}

// ---------------- tensor-core GEMM1 (R5/R10 config) ---------------------------
#define MMA_BF16(c, a0, a1, a2, a3, b0, b1)                                    \
    asm volatile(                                                              \
        "mma.sync.aligned.m16n8k16.row.col.f32.bf16.bf16.f32 "                 \
        "{%0,%1,%2,%3}, {%4,%5,%6,%7}, {%8,%9}, {%0,%1,%2,%3};\n"              \
        : "+f"(c[0]), "+f"(c[1]), "+f"(c[2]), "+f"(c[3])                       \
        : "r"(a0), "r"(a1), "r"(a2), "r"(a3), "r"(b0), "r"(b1))

__device__ __forceinline__ void ldm4(uint32_t* r, uint32_t saddr) {
    asm volatile("ldmatrix.sync.aligned.m8n8.x4.shared.b16 {%0,%1,%2,%3}, [%4];"
                 : "=r"(r[0]), "=r"(r[1]), "=r"(r[2]), "=r"(r[3]) : "r"(saddr));
}

__global__ void __launch_bounds__(256, 2) sgemm1_tc_kernel() {
    __shared__ uint32_t As_hi[2][128 * 8];
    __shared__ uint32_t As_lo[2][128 * 8];
    __shared__ uint32_t Bs_hi[2][128 * 8];
    __shared__ uint32_t Bs_lo[2][128 * 8];

    const int t = threadIdx.x, lane = t & 31, wid = t >> 5;
    const int warpM = wid >> 1, warpN = wid & 1;
    const int rowBase = blockIdx.y * 128, colBase = blockIdx.x * 128;

    const int lrow  = t >> 1;
    const int lhalf = t & 1;
    const int arow_g = rowBase + lrow;
    const bool avalid = arow_g < NN;
    const size_t a_base = (size_t)(avalid ? arow_g : 0) * (FIN / 2) + lhalf * 4;
    const size_t b_base = (size_t)(colBase + lrow) * (FIN / 2) + lhalf * 4;
    const int s_off = lrow * 8 + ((lhalf * 4) ^ (lrow & 4));

    const int lr = lane & 15, kq = lane >> 4;
    uint32_t off_a[2], off_b[4];
#pragma unroll
    for (int mt = 0; mt < 2; mt++) {
        int r = warpM * 32 + mt * 16 + lr;
        off_a[mt] = (uint32_t)(r * 8 + ((kq * 4) ^ (r & 4))) * 4u;
    }
#pragma unroll
    for (int np = 0; np < 4; np++) {
        int r = warpN * 64 + np * 16 + lr;
        off_b[np] = (uint32_t)(r * 8 + ((kq * 4) ^ (r & 4))) * 4u;
    }
    uint32_t baseAh[2], baseAl[2], baseBh[2], baseBl[2];
#pragma unroll
    for (int b = 0; b < 2; b++) {
        baseAh[b] = (uint32_t)__cvta_generic_to_shared(&As_hi[b][0]);
        baseAl[b] = (uint32_t)__cvta_generic_to_shared(&As_lo[b][0]);
        baseBh[b] = (uint32_t)__cvta_generic_to_shared(&Bs_hi[b][0]);
        baseBl[b] = (uint32_t)__cvta_generic_to_shared(&Bs_lo[b][0]);
    }

    float acc[2][8][4];
#pragma unroll
    for (int mt = 0; mt < 2; mt++)
#pragma unroll
        for (int nt = 0; nt < 8; nt++)
#pragma unroll
            for (int q = 0; q < 4; q++) acc[mt][nt][q] = 0.f;

    const uint4 z4 = make_uint4(0, 0, 0, 0);
    uint4 ra_h, ra_l, rb_h, rb_l;

    ra_h = avalid ? *(const uint4*)&g_xhi[a_base] : z4;
    ra_l = avalid ? *(const uint4*)&g_xlo[a_base] : z4;
    rb_h = *(const uint4*)&g_w1t_hi[b_base];
    rb_l = *(const uint4*)&g_w1t_lo[b_base];
    *(uint4*)&As_hi[0][s_off] = ra_h;
    *(uint4*)&As_lo[0][s_off] = ra_l;
    *(uint4*)&Bs_hi[0][s_off] = rb_h;
    *(uint4*)&Bs_lo[0][s_off] = rb_l;
    __syncthreads();

    const int NSTAGE = FIN / 16;    // 32
    for (int ks = 0; ks < NSTAGE; ks++) {
        const int cur = ks & 1;
        if (ks + 1 < NSTAGE) {
            size_t off = (size_t)(ks + 1) * 8;
            ra_h = avalid ? *(const uint4*)&g_xhi[a_base + off] : z4;
            ra_l = avalid ? *(const uint4*)&g_xlo[a_base + off] : z4;
            rb_h = *(const uint4*)&g_w1t_hi[b_base + off];
            rb_l = *(const uint4*)&g_w1t_lo[b_base + off];
        }

        uint32_t afh[2][4], afl[2][4];
        ldm4(afh[0], baseAh[cur] + off_a[0]);
        ldm4(afh[1], baseAh[cur] + off_a[1]);
        ldm4(afl[0], baseAl[cur] + off_a[0]);
        ldm4(afl[1], baseAl[cur] + off_a[1]);

#pragma unroll
        for (int np = 0; np < 4; np++) {
            uint32_t bh[4], bl[4];
            ldm4(bh, baseBh[cur] + off_b[np]);
            ldm4(bl, baseBl[cur] + off_b[np]);
#pragma unroll
            for (int mt = 0; mt < 2; mt++) {
                MMA_BF16(acc[mt][2 * np],     afh[mt][0], afh[mt][1], afh[mt][2], afh[mt][3], bh[0], bh[2]);
                MMA_BF16(acc[mt][2 * np],     afh[mt][0], afh[mt][1], afh[mt][2], afh[mt][3], bl[0], bl[2]);
                MMA_BF16(acc[mt][2 * np],     afl[mt][0], afl[mt][1], afl[mt][2], afl[mt][3], bh[0], bh[2]);
                MMA_BF16(acc[mt][2 * np + 1], afh[mt][0], afh[mt][1], afh[mt][2], afh[mt][3], bh[1], bh[3]);
                MMA_BF16(acc[mt][2 * np + 1], afh[mt][0], afh[mt][1], afh[mt][2], afh[mt][3], bl[1], bl[3]);
                MMA_BF16(acc[mt][2 * np + 1], afl[mt][0], afl[mt][1], afl[mt][2], afl[mt][3], bh[1], bh[3]);
            }
        }
        if (ks + 1 < NSTAGE) {
            const int nxt = 1 - cur;
            *(uint4*)&As_hi[nxt][s_off] = ra_h;
            *(uint4*)&As_lo[nxt][s_off] = ra_l;
            *(uint4*)&Bs_hi[nxt][s_off] = rb_h;
            *(uint4*)&Bs_lo[nxt][s_off] = rb_l;
            __syncthreads();
        }
    }

#pragma unroll
    for (int mt = 0; mt < 2; mt++) {
        const int r = rowBase + warpM * 32 + mt * 16 + (lane >> 2);
#pragma unroll
        for (int nt = 0; nt < 8; nt++) {
            const int c = colBase + warpN * 64 + nt * 8 + (lane & 3) * 2;
            if (r < NN) {
                float2 v = make_float2(acc[mt][nt][0], acc[mt][nt][1]);
                *(float2*)&g_h1[(size_t)r * D1 + c] = v;
            }
            if (r + 8 < NN) {
                float2 v = make_float2(acc[mt][nt][2], acc[mt][nt][3]);
                *(float2*)&g_h1[(size_t)(r + 8) * D1 + c] = v;
            }
        }
    }
}

// ---------------- alpha1: per-node attention logits (warp per node) ----------
__global__ void alpha1_kernel(const float* __restrict__ a_src, const float* __restrict__ a_dst) {
    int gw = (blockIdx.x * blockDim.x + threadIdx.x) >> 5;
    int lane = threadIdx.x & 31;
    if (gw >= NN) return;
    const float* hp = &g_h1[(size_t)gw * D1];
#pragma unroll
    for (int h = 0; h < H1; h++) {
        float v = hp[h * 32 + lane];
        float s1 = v * __ldg(&a_src[h * 32 + lane]);
        float s2 = v * __ldg(&a_dst[h * 32 + lane]);
#pragma unroll
        for (int off = 16; off > 0; off >>= 1) {
            s1 += __shfl_xor_sync(0xffffffffu, s1, off);
            s2 += __shfl_xor_sync(0xffffffffu, s2, off);
        }
        if (lane == 0) {
            g_as1[gw * H1 + h] = s1;
            g_ad1[gw * H1 + h] = s2;
        }
    }
}

// ---------------- CSR build ---------------------------------------------------
__global__ void zero_deg_kernel() {
    int i = blockIdx.x * blockDim.x + threadIdx.x;
    if (i < NN) g_deg[i] = 0;
}

__global__ void hist_kernel(const int* __restrict__ ei) {
    int i = blockIdx.x * blockDim.x + threadIdx.x;
    if (i >= E2) return;
    int d = (i < EE) ? __ldg(&ei[EE + i]) : (i - EE);
    atomicAdd(&g_deg[d], 1);
}

__global__ void scan_block_kernel() {
    __shared__ int sh[1024];
    int tid = threadIdx.x;
    int i = blockIdx.x * 1024 + tid;
    int v = (i < NN) ? g_deg[i] : 0;
    sh[tid] = v;
    __syncthreads();
#pragma unroll
    for (int off = 1; off < 1024; off <<= 1) {
        int t = (tid >= off) ? sh[tid - off] : 0;
        __syncthreads();
        sh[tid] += t;
        __syncthreads();
    }
    if (i < NN) g_incl[i] = sh[tid];
    if (tid == 1023) g_parts[blockIdx.x] = sh[tid];
}

__global__ void scan_parts_kernel(int nb) {
    __shared__ int sh[64];
    int tid = threadIdx.x;
    int v = (tid < nb) ? g_parts[tid] : 0;
    sh[tid] = v;
    __syncthreads();
#pragma unroll
    for (int off = 1; off < 64; off <<= 1) {
        int t = (tid >= off) ? sh[tid - off] : 0;
        __syncthreads();
        sh[tid] += t;
        __syncthreads();
    }
    if (tid < nb) g_parts_ex[tid] = sh[tid] - v;
}

__global__ void finalize_scan_kernel() {
    int i = blockIdx.x * blockDim.x + threadIdx.x;
    if (i >= NN) return;
    int start = g_incl[i] - g_deg[i] + g_parts_ex[i >> 10];
    g_starts[i] = start;
    g_cursor[i] = start;
}

__global__ void fill_kernel(const int* __restrict__ ei) {
    int i = blockIdx.x * blockDim.x + threadIdx.x;
    if (i >= E2) return;
    int s, d;
    if (i < EE) { s = __ldg(&ei[i]); d = __ldg(&ei[EE + i]); }
    else        { s = i - EE; d = s; }
    int p = atomicAdd(&g_cursor[d], 1);
    g_ssrc[p] = s;
}

// ---------------- layer1 aggregation (warp per dst node, all heads) -----------
__global__ void agg1_kernel(const float* __restrict__ b1) {
    int n = (blockIdx.x * blockDim.x + threadIdx.x) >> 5;
    int lane = threadIdx.x & 31;
    if (n >= NN) return;
    int st = g_starts[n];
    int d  = g_deg[n];

    float adh[H1];
#pragma unroll
    for (int h = 0; h < H1; h++) adh[h] = g_ad1[n * H1 + h];

    float den[H1];
#pragma unroll
    for (int h = 0; h < H1; h++) den[h] = 0.f;
    for (int j = lane; j < d; j += 32) {
        int s = __ldg(&g_ssrc[st + j]);
        float* wp = &g_wbuf[(size_t)(st + j) * H1];
        const float* asp = &g_as1[s * H1];
#pragma unroll
        for (int h = 0; h < H1; h++) {
            float e = __ldg(&asp[h]) + adh[h];
            e = fmaxf(e, 0.2f * e);
            float ex = __expf(e);
            wp[h] = ex;
            den[h] += ex;
        }
    }
#pragma unroll
    for (int h = 0; h < H1; h++) {
#pragma unroll
        for (int off = 16; off > 0; off >>= 1)
            den[h] += __shfl_xor_sync(0xffffffffu, den[h], off);
    }
    float inv[H1];
#pragma unroll
    for (int h = 0; h < H1; h++) inv[h] = 1.f / (den[h] + 1e-16f);

    float acc[H1];
#pragma unroll
    for (int h = 0; h < H1; h++) acc[h] = 0.f;
#pragma unroll 4
    for (int j = 0; j < d; j++) {
        int s = __ldg(&g_ssrc[st + j]);
        const float* wp = &g_wbuf[(size_t)(st + j) * H1];
        const float* hp = &g_h1[(size_t)s * D1];
#pragma unroll
        for (int h = 0; h < H1; h++) {
            float w = wp[h] * inv[h];
            acc[h] = fmaf(__ldg(&hp[h * 32 + lane]), w, acc[h]);
        }
    }

#pragma unroll
    for (int h = 0; h < H1; h++) {
        float v = acc[h] + __ldg(&b1[h * 32 + lane]);
        v = (v > 0.f) ? v : expm1f(v);
        g_hout1[(size_t)n * D1 + h * 32 + lane] = v;
    }
}

// ---------------- layer2 linear + alpha2 --------------------------------------
__global__ void layer2_linear_kernel(const float* __restrict__ W2,
                                     const float* __restrict__ a_src2,
                                     const float* __restrict__ a_dst2) {
    __shared__ float Ws[D1 * CLS + 64];
    __shared__ float as_sh[CLS], ad_sh[CLS];
    int tid = threadIdx.x;
    for (int i = tid; i < D1 * CLS + 64; i += blockDim.x)
        Ws[i] = (i < D1 * CLS) ? W2[i] : 0.f;
    if (tid < CLS) { as_sh[tid] = a_src2[tid]; ad_sh[tid] = a_dst2[tid]; }
    __syncthreads();

    int lane = tid & 31;
    int warpsPerBlock = blockDim.x >> 5;
    int gw = blockIdx.x * warpsPerBlock + (tid >> 5);
    int stride = gridDim.x * warpsPerBlock;

    for (int n = gw; n < NN; n += stride) {
        const float* xp = &g_hout1[(size_t)n * D1];
        float acc0a = 0.f, acc0b = 0.f, acc1a = 0.f, acc1b = 0.f;
#pragma unroll
        for (int kb = 0; kb < D1 / 32; kb++) {
            float xv = xp[kb * 32 + lane];
#pragma unroll
            for (int j = 0; j < 32; j += 2) {
                float xj0 = __shfl_sync(0xffffffffu, xv, j);
                float xj1 = __shfl_sync(0xffffffffu, xv, j + 1);
                int k0 = kb * 32 + j;
                acc0a = fmaf(xj0, Ws[k0 * CLS + lane], acc0a);
                acc1a = fmaf(xj0, Ws[k0 * CLS + 32 + lane], acc1a);
                acc0b = fmaf(xj1, Ws[(k0 + 1) * CLS + lane], acc0b);
                acc1b = fmaf(xj1, Ws[(k0 + 1) * CLS + 32 + lane], acc1b);
            }
        }
        float v0 = acc0a + acc0b;
        float v1 = acc1a + acc1b;
        g_h2lin[(size_t)n * CLSP + lane] = v0;
        if (lane < CLS - 32) g_h2lin[(size_t)n * CLSP + 32 + lane] = v1;
        float ps = v0 * as_sh[lane] + ((lane < CLS - 32) ? v1 * as_sh[32 + lane] : 0.f);
        float pd = v0 * ad_sh[lane] + ((lane < CLS - 32) ? v1 * ad_sh[32 + lane] : 0.f);
#pragma unroll
        for (int off = 16; off > 0; off >>= 1) {
            ps += __shfl_xor_sync(0xffffffffu, ps, off);
            pd += __shfl_xor_sync(0xffffffffu, pd, off);
        }
        if (lane == 0) { g_as2[n] = ps; g_ad2[n] = pd; }
    }
}

// ---------------- layer2 aggregation + log_softmax ----------------------------
__global__ void agg2_kernel(const float* __restrict__ b2, float* __restrict__ out) {
    int n = (blockIdx.x * blockDim.x + threadIdx.x) >> 5;
    int lane = threadIdx.x & 31;
    if (n >= NN) return;
    int st = g_starts[n];
    int d  = g_deg[n];
    float adn = g_ad2[n];

    float den = 0.f;
    for (int j = lane; j < d; j += 32) {
        int s = __ldg(&g_ssrc[st + j]);
        float e = __ldg(&g_as2[s]) + adn;
        e = fmaxf(e, 0.2f * e);
        float ex = __expf(e);
        g_wbuf2[st + j] = ex;
        den += ex;
    }
#pragma unroll
    for (int off = 16; off > 0; off >>= 1)
        den += __shfl_xor_sync(0xffffffffu, den, off);
    float inv = 1.f / (den + 1e-16f);

    float acc0 = 0.f, acc1 = 0.f;
#pragma unroll 4
    for (int j = 0; j < d; j++) {
        int s = __ldg(&g_ssrc[st + j]);
        float w = g_wbuf2[st + j] * inv;
        const float* hp = &g_h2lin[(size_t)s * CLSP];
        acc0 = fmaf(__ldg(&hp[lane]), w, acc0);
        if (lane < CLS - 32) acc1 = fmaf(__ldg(&hp[32 + lane]), w, acc1);
    }
    float v0 = acc0 + __ldg(&b2[lane]);
    float v1 = (lane < CLS - 32) ? (acc1 + __ldg(&b2[32 + lane])) : -CUDART_INF_F;

    float m = fmaxf(v0, v1);
#pragma unroll
    for (int off = 16; off > 0; off >>= 1)
        m = fmaxf(m, __shfl_xor_sync(0xffffffffu, m, off));
    float s0 = __expf(v0 - m) + ((lane < CLS - 32) ? __expf(v1 - m) : 0.f);
#pragma unroll
    for (int off = 16; off > 0; off >>= 1)
        s0 += __shfl_xor_sync(0xffffffffu, s0, off);
    float lse = m + logf(s0);

    out[(size_t)n * CLS + lane] = v0 - lse;
    if (lane < CLS - 32) out[(size_t)n * CLS + 32 + lane] = v1 - lse;
}

// ---------------- launch ------------------------------------------------------
extern "C" void kernel_launch(void* const* d_in, const int* in_sizes, int n_in,
                              void* d_out, int out_size) {
    const float* x      = (const float*)d_in[0];
    const int*   ei     = (const int*)d_in[1];
    const float* W1     = (const float*)d_in[2];
    const float* a_src1 = (const float*)d_in[3];
    const float* a_dst1 = (const float*)d_in[4];
    const float* b1     = (const float*)d_in[5];
    const float* W2     = (const float*)d_in[6];
    const float* a_src2 = (const float*)d_in[7];
    const float* a_dst2 = (const float*)d_in[8];
    const float* b2     = (const float*)d_in[9];
    float* out = (float*)d_out;

    const int nb_scan = (NN + 1023) / 1024;   // 49

    // one-time side-stream/event creation (first call is the uncaptured
    // correctness run; during capture only record/wait are used)
    static cudaStream_t s2 = nullptr;
    static cudaEvent_t evFork = nullptr, evCSR = nullptr;
    if (s2 == nullptr) {
        cudaStreamCreateWithFlags(&s2, cudaStreamNonBlocking);
        cudaEventCreateWithFlags(&evFork, cudaEventDisableTiming);
        cudaEventCreateWithFlags(&evCSR, cudaEventDisableTiming);
    }

    // fork: CSR build chain on side stream, concurrent with prep+GEMM+alpha1
    cudaEventRecord(evFork, 0);
    cudaStreamWaitEvent(s2, evFork, 0);
    zero_deg_kernel<<<(NN + 255) / 256, 256, 0, s2>>>();
    hist_kernel<<<(E2 + 255) / 256, 256, 0, s2>>>(ei);
    scan_block_kernel<<<nb_scan, 1024, 0, s2>>>();
    scan_parts_kernel<<<1, 64, 0, s2>>>(nb_scan);
    finalize_scan_kernel<<<(NN + 255) / 256, 256, 0, s2>>>();
    fill_kernel<<<(E2 + 255) / 256, 256, 0, s2>>>(ei);
    cudaEventRecord(evCSR, s2);

    // main stream: prep, GEMM (slot stays early for ncu window), alpha1
    prep_x_kernel<<<(NN * FIN / 4 + 255) / 256, 256>>>(x);
    prep_w_kernel<<<(D1 * (FIN / 2) + 255) / 256, 256>>>(W1);
    sgemm1_tc_kernel<<<dim3(2, (NN + 127) / 128), 256>>>();
    alpha1_kernel<<<(NN * 32 + 255) / 256, 256>>>(a_src1, a_dst1);

    // join: agg1 needs CSR + alpha1
    cudaStreamWaitEvent(0, evCSR, 0);
    agg1_kernel<<<(NN * 32 + 255) / 256, 256>>>(b1);

    // layer 2
    layer2_linear_kernel<<<592, 256>>>(W2, a_src2, a_dst2);
    agg2_kernel<<<(NN * 32 + 255) / 256, 256>>>(b2, out);
}

// round 12
// speedup vs baseline: 1.2004x; 1.1135x over previous
#include <cuda_runtime.h>
#include <cuda_bf16.h>
#include <math_constants.h>
#include <cstdint>

// Problem constants (fixed by the dataset)
#define NN   50000
#define EE   800000
#define E2   (EE + NN)      // edges + self loops = 850000
#define FIN  512
#define H1   8
#define C1   32
#define D1   (H1 * C1)      // 256
#define CLS  40
#define CLSP 64              // padded h2lin row (256B aligned)

// ---------------- scratch (static device globals; no runtime alloc) ----------
__device__ float g_h1[NN * D1];          // layer1 linear output [N,256] fp32
__device__ uint32_t g_h1b[NN * (D1/2)];  // bf16x2-packed h1 for agg1 gather
__device__ float g_as1[NN * H1];
__device__ float g_ad1[NN * H1];
__device__ float g_hout1[NN * D1];       // elu(agg1 + b1) [N,256]
__device__ float g_h2lin[NN * CLSP];     // layer2 linear output, padded rows
__device__ float g_as2[NN];
__device__ float g_ad2[NN];
__device__ float g_wbuf[E2 * H1];        // per-edge exp(logit), interleaved [edge][h]
__device__ float g_wbuf2[E2];
__device__ int   g_deg[NN];
__device__ int   g_incl[NN];
__device__ int   g_starts[NN];
__device__ int   g_cursor[NN];
__device__ int   g_ssrc[E2];
__device__ int   g_parts[64];
__device__ int   g_parts_ex[64];
// bf16 split-precision operands for GEMM1
__device__ uint32_t g_xhi[NN * (FIN / 2)];
__device__ uint32_t g_xlo[NN * (FIN / 2)];
__device__ uint32_t g_w1t_hi[D1 * (FIN / 2)];
__device__ uint32_t g_w1t_lo[D1 * (FIN / 2)];

// ---------------- bf16 split helpers -----------------------------------------
__device__ __forceinline__ void split2(float x, float y, uint32_t& hi, uint32_t& lo) {
    __nv_bfloat16 hx = __float2bfloat16_rn(x);
    __nv_bfloat16 hy = __float2bfloat16_rn(y);
    float lxf = x - __bfloat162float(hx);
    float lyf = y - __bfloat162float(hy);
    __nv_bfloat162 hv; hv.x = hx; hv.y = hy;
    __nv_bfloat162 lv = __floats2bfloat162_rn(lxf, lyf);
    hi = *reinterpret_cast<uint32_t*>(&hv);
    lo = *reinterpret_cast<uint32_t*>(&lv);
}

__global__ void prep_x_kernel(const float* __restrict__ x) {
    int i = blockIdx.x * blockDim.x + threadIdx.x;
    const int NQ = NN * FIN / 4;
    if (i >= NQ) return;
    float4 v = ((const float4*)x)[i];
    uint32_t h0, l0, h1, l1;
    split2(v.x, v.y, h0, l0);
    split2(v.z, v.w, h1, l1);
    g_xhi[2 * i]     = h0;  g_xhi[2 * i + 1] = h1;
    g_xlo[2 * i]     = l0;  g_xlo[2 * i + 1] = l1;
}

__global__ void prep_w_kernel(const float* __restrict__ W1) {
    int idx = blockIdx.x * blockDim.x + threadIdx.x;
    if (idx >= D1 * (FIN / 2)) return;
    int n = idx >> 8;
    int kp = idx & 255;
    float a = W1[(size_t)(2 * kp) * D1 + n];
    float b = W1[(size_t)(2 * kp + 1) * D1 + n];
    uint32_t hi, lo;
    split2(a, b, hi, lo);
    g_w1t_hi[idx] = hi;
    g_w1t_lo[idx] = lo;
}

// ---------------- tensor-core GEMM1 (R5/R10 config) ---------------------------
#define MMA_BF16(c, a0, a1, a2, a3, b0, b1)                                    \
    asm volatile(                                                              \
        "mma.sync.aligned.m16n8k16.row.col.f32.bf16.bf16.f32 "                 \
        "{%0,%1,%2,%3}, {%4,%5,%6,%7}, {%8,%9}, {%0,%1,%2,%3};\n"              \
        : "+f"(c[0]), "+f"(c[1]), "+f"(c[2]), "+f"(c[3])                       \
        : "r"(a0), "r"(a1), "r"(a2), "r"(a3), "r"(b0), "r"(b1))

__device__ __forceinline__ void ldm4(uint32_t* r, uint32_t saddr) {
    asm volatile("ldmatrix.sync.aligned.m8n8.x4.shared.b16 {%0,%1,%2,%3}, [%4];"
                 : "=r"(r[0]), "=r"(r[1]), "=r"(r[2]), "=r"(r[3]) : "r"(saddr));
}

__global__ void __launch_bounds__(256, 2) sgemm1_tc_kernel() {
    __shared__ uint32_t As_hi[2][128 * 8];
    __shared__ uint32_t As_lo[2][128 * 8];
    __shared__ uint32_t Bs_hi[2][128 * 8];
    __shared__ uint32_t Bs_lo[2][128 * 8];

    const int t = threadIdx.x, lane = t & 31, wid = t >> 5;
    const int warpM = wid >> 1, warpN = wid & 1;
    const int rowBase = blockIdx.y * 128, colBase = blockIdx.x * 128;

    const int lrow  = t >> 1;
    const int lhalf = t & 1;
    const int arow_g = rowBase + lrow;
    const bool avalid = arow_g < NN;
    const size_t a_base = (size_t)(avalid ? arow_g : 0) * (FIN / 2) + lhalf * 4;
    const size_t b_base = (size_t)(colBase + lrow) * (FIN / 2) + lhalf * 4;
    const int s_off = lrow * 8 + ((lhalf * 4) ^ (lrow & 4));

    const int lr = lane & 15, kq = lane >> 4;
    uint32_t off_a[2], off_b[4];
#pragma unroll
    for (int mt = 0; mt < 2; mt++) {
        int r = warpM * 32 + mt * 16 + lr;
        off_a[mt] = (uint32_t)(r * 8 + ((kq * 4) ^ (r & 4))) * 4u;
    }
#pragma unroll
    for (int np = 0; np < 4; np++) {
        int r = warpN * 64 + np * 16 + lr;
        off_b[np] = (uint32_t)(r * 8 + ((kq * 4) ^ (r & 4))) * 4u;
    }
    uint32_t baseAh[2], baseAl[2], baseBh[2], baseBl[2];
#pragma unroll
    for (int b = 0; b < 2; b++) {
        baseAh[b] = (uint32_t)__cvta_generic_to_shared(&As_hi[b][0]);
        baseAl[b] = (uint32_t)__cvta_generic_to_shared(&As_lo[b][0]);
        baseBh[b] = (uint32_t)__cvta_generic_to_shared(&Bs_hi[b][0]);
        baseBl[b] = (uint32_t)__cvta_generic_to_shared(&Bs_lo[b][0]);
    }

    float acc[2][8][4];
#pragma unroll
    for (int mt = 0; mt < 2; mt++)
#pragma unroll
        for (int nt = 0; nt < 8; nt++)
#pragma unroll
            for (int q = 0; q < 4; q++) acc[mt][nt][q] = 0.f;

    const uint4 z4 = make_uint4(0, 0, 0, 0);
    uint4 ra_h, ra_l, rb_h, rb_l;

    ra_h = avalid ? *(const uint4*)&g_xhi[a_base] : z4;
    ra_l = avalid ? *(const uint4*)&g_xlo[a_base] : z4;
    rb_h = *(const uint4*)&g_w1t_hi[b_base];
    rb_l = *(const uint4*)&g_w1t_lo[b_base];
    *(uint4*)&As_hi[0][s_off] = ra_h;
    *(uint4*)&As_lo[0][s_off] = ra_l;
    *(uint4*)&Bs_hi[0][s_off] = rb_h;
    *(uint4*)&Bs_lo[0][s_off] = rb_l;
    __syncthreads();

    const int NSTAGE = FIN / 16;    // 32
    for (int ks = 0; ks < NSTAGE; ks++) {
        const int cur = ks & 1;
        if (ks + 1 < NSTAGE) {
            size_t off = (size_t)(ks + 1) * 8;
            ra_h = avalid ? *(const uint4*)&g_xhi[a_base + off] : z4;
            ra_l = avalid ? *(const uint4*)&g_xlo[a_base + off] : z4;
            rb_h = *(const uint4*)&g_w1t_hi[b_base + off];
            rb_l = *(const uint4*)&g_w1t_lo[b_base + off];
        }

        uint32_t afh[2][4], afl[2][4];
        ldm4(afh[0], baseAh[cur] + off_a[0]);
        ldm4(afh[1], baseAh[cur] + off_a[1]);
        ldm4(afl[0], baseAl[cur] + off_a[0]);
        ldm4(afl[1], baseAl[cur] + off_a[1]);

#pragma unroll
        for (int np = 0; np < 4; np++) {
            uint32_t bh[4], bl[4];
            ldm4(bh, baseBh[cur] + off_b[np]);
            ldm4(bl, baseBl[cur] + off_b[np]);
#pragma unroll
            for (int mt = 0; mt < 2; mt++) {
                MMA_BF16(acc[mt][2 * np],     afh[mt][0], afh[mt][1], afh[mt][2], afh[mt][3], bh[0], bh[2]);
                MMA_BF16(acc[mt][2 * np],     afh[mt][0], afh[mt][1], afh[mt][2], afh[mt][3], bl[0], bl[2]);
                MMA_BF16(acc[mt][2 * np],     afl[mt][0], afl[mt][1], afl[mt][2], afl[mt][3], bh[0], bh[2]);
                MMA_BF16(acc[mt][2 * np + 1], afh[mt][0], afh[mt][1], afh[mt][2], afh[mt][3], bh[1], bh[3]);
                MMA_BF16(acc[mt][2 * np + 1], afh[mt][0], afh[mt][1], afh[mt][2], afh[mt][3], bl[1], bl[3]);
                MMA_BF16(acc[mt][2 * np + 1], afl[mt][0], afl[mt][1], afl[mt][2], afl[mt][3], bh[1], bh[3]);
            }
        }
        if (ks + 1 < NSTAGE) {
            const int nxt = 1 - cur;
            *(uint4*)&As_hi[nxt][s_off] = ra_h;
            *(uint4*)&As_lo[nxt][s_off] = ra_l;
            *(uint4*)&Bs_hi[nxt][s_off] = rb_h;
            *(uint4*)&Bs_lo[nxt][s_off] = rb_l;
            __syncthreads();
        }
    }

#pragma unroll
    for (int mt = 0; mt < 2; mt++) {
        const int r = rowBase + warpM * 32 + mt * 16 + (lane >> 2);
#pragma unroll
        for (int nt = 0; nt < 8; nt++) {
            const int c = colBase + warpN * 64 + nt * 8 + (lane & 3) * 2;
            if (r < NN) {
                *(float2*)&g_h1[(size_t)r * D1 + c] = make_float2(acc[mt][nt][0], acc[mt][nt][1]);
                __nv_bfloat162 bv = __floats2bfloat162_rn(acc[mt][nt][0], acc[mt][nt][1]);
                g_h1b[(size_t)r * (D1/2) + (c >> 1)] = *reinterpret_cast<uint32_t*>(&bv);
            }
            if (r + 8 < NN) {
                *(float2*)&g_h1[(size_t)(r + 8) * D1 + c] = make_float2(acc[mt][nt][2], acc[mt][nt][3]);
                __nv_bfloat162 bv = __floats2bfloat162_rn(acc[mt][nt][2], acc[mt][nt][3]);
                g_h1b[(size_t)(r + 8) * (D1/2) + (c >> 1)] = *reinterpret_cast<uint32_t*>(&bv);
            }
        }
    }
}

// ---------------- alpha1: per-node attention logits (warp per node) ----------
__global__ void alpha1_kernel(const float* __restrict__ a_src, const float* __restrict__ a_dst) {
    int gw = (blockIdx.x * blockDim.x + threadIdx.x) >> 5;
    int lane = threadIdx.x & 31;
    if (gw >= NN) return;
    const float* hp = &g_h1[(size_t)gw * D1];
#pragma unroll
    for (int h = 0; h < H1; h++) {
        float v = hp[h * 32 + lane];
        float s1 = v * __ldg(&a_src[h * 32 + lane]);
        float s2 = v * __ldg(&a_dst[h * 32 + lane]);
#pragma unroll
        for (int off = 16; off > 0; off >>= 1) {
            s1 += __shfl_xor_sync(0xffffffffu, s1, off);
            s2 += __shfl_xor_sync(0xffffffffu, s2, off);
        }
        if (lane == 0) {
            g_as1[gw * H1 + h] = s1;
            g_ad1[gw * H1 + h] = s2;
        }
    }
}

// ---------------- CSR build ---------------------------------------------------
__global__ void zero_deg_kernel() {
    int i = blockIdx.x * blockDim.x + threadIdx.x;
    if (i < NN) g_deg[i] = 0;
}

__global__ void hist_kernel(const int* __restrict__ ei) {
    int i = blockIdx.x * blockDim.x + threadIdx.x;
    if (i >= E2) return;
    int d = (i < EE) ? __ldg(&ei[EE + i]) : (i - EE);
    atomicAdd(&g_deg[d], 1);
}

__global__ void scan_block_kernel() {
    __shared__ int sh[1024];
    int tid = threadIdx.x;
    int i = blockIdx.x * 1024 + tid;
    int v = (i < NN) ? g_deg[i] : 0;
    sh[tid] = v;
    __syncthreads();
#pragma unroll
    for (int off = 1; off < 1024; off <<= 1) {
        int t = (tid >= off) ? sh[tid - off] : 0;
        __syncthreads();
        sh[tid] += t;
        __syncthreads();
    }
    if (i < NN) g_incl[i] = sh[tid];
    if (tid == 1023) g_parts[blockIdx.x] = sh[tid];
}

__global__ void scan_parts_kernel(int nb) {
    __shared__ int sh[64];
    int tid = threadIdx.x;
    int v = (tid < nb) ? g_parts[tid] : 0;
    sh[tid] = v;
    __syncthreads();
#pragma unroll
    for (int off = 1; off < 64; off <<= 1) {
        int t = (tid >= off) ? sh[tid - off] : 0;
        __syncthreads();
        sh[tid] += t;
        __syncthreads();
    }
    if (tid < nb) g_parts_ex[tid] = sh[tid] - v;
}

__global__ void finalize_scan_kernel() {
    int i = blockIdx.x * blockDim.x + threadIdx.x;
    if (i >= NN) return;
    int start = g_incl[i] - g_deg[i] + g_parts_ex[i >> 10];
    g_starts[i] = start;
    g_cursor[i] = start;
}

__global__ void fill_kernel(const int* __restrict__ ei) {
    int i = blockIdx.x * blockDim.x + threadIdx.x;
    if (i >= E2) return;
    int s, d;
    if (i < EE) { s = __ldg(&ei[i]); d = __ldg(&ei[EE + i]); }
    else        { s = i - EE; d = s; }
    int p = atomicAdd(&g_cursor[d], 1);
    g_ssrc[p] = s;
}

// ---------------- layer1 aggregation (warp per dst node, bf16 gather) ---------
__global__ void agg1_kernel(const float* __restrict__ b1) {
    int n = (blockIdx.x * blockDim.x + threadIdx.x) >> 5;
    int lane = threadIdx.x & 31;
    if (n >= NN) return;
    int st = g_starts[n];
    int d  = g_deg[n];

    float adh[H1];
#pragma unroll
    for (int h = 0; h < H1; h++) adh[h] = g_ad1[n * H1 + h];

    // pass A: per-edge exp for all heads + denominators (fp32 logits)
    float den[H1];
#pragma unroll
    for (int h = 0; h < H1; h++) den[h] = 0.f;
    for (int j = lane; j < d; j += 32) {
        int s = __ldg(&g_ssrc[st + j]);
        float* wp = &g_wbuf[(size_t)(st + j) * H1];
        const float* asp = &g_as1[s * H1];
#pragma unroll
        for (int h = 0; h < H1; h++) {
            float e = __ldg(&asp[h]) + adh[h];
            e = fmaxf(e, 0.2f * e);
            float ex = __expf(e);
            wp[h] = ex;
            den[h] += ex;
        }
    }
#pragma unroll
    for (int h = 0; h < H1; h++) {
#pragma unroll
        for (int off = 16; off > 0; off >>= 1)
            den[h] += __shfl_xor_sync(0xffffffffu, den[h], off);
    }
    float inv[H1];
#pragma unroll
    for (int h = 0; h < H1; h++) inv[h] = 1.f / (den[h] + 1e-16f);

    // per-lane head for each q: pair index p = 32q + lane, head = 2q + (lane>>4)
    float invq[4];
#pragma unroll
    for (int q = 0; q < 4; q++)
        invq[q] = (lane >= 16) ? inv[2 * q + 1] : inv[2 * q];
    const int hsel = lane >> 4;

    // pass B: bf16x2 gather — 512B per edge per warp (half of fp32)
    float2 acc2[4];
#pragma unroll
    for (int q = 0; q < 4; q++) acc2[q] = make_float2(0.f, 0.f);
#pragma unroll 4
    for (int j = 0; j < d; j++) {
        int s = __ldg(&g_ssrc[st + j]);
        const float* wp = &g_wbuf[(size_t)(st + j) * H1];
        const uint32_t* hb = &g_h1b[(size_t)s * (D1/2)];
#pragma unroll
        for (int q = 0; q < 4; q++) {
            float w = wp[2 * q + hsel] * invq[q];
            uint32_t u = __ldg(&hb[32 * q + lane]);
            __nv_bfloat162 bv = *reinterpret_cast<__nv_bfloat162*>(&u);
            float2 f = __bfloat1622float2(bv);
            acc2[q].x = fmaf(f.x, w, acc2[q].x);
            acc2[q].y = fmaf(f.y, w, acc2[q].y);
        }
    }

    // epilogue: +bias, ELU, store (pair p = 32q+lane → channels 2p, 2p+1)
#pragma unroll
    for (int q = 0; q < 4; q++) {
        int c0 = (32 * q + lane) * 2;
        float2 bb = *(const float2*)&b1[c0];
        float v0 = acc2[q].x + bb.x;
        float v1 = acc2[q].y + bb.y;
        v0 = (v0 > 0.f) ? v0 : expm1f(v0);
        v1 = (v1 > 0.f) ? v1 : expm1f(v1);
        *(float2*)&g_hout1[(size_t)n * D1 + c0] = make_float2(v0, v1);
    }
}

// ---------------- layer2 linear + alpha2 --------------------------------------
__global__ void layer2_linear_kernel(const float* __restrict__ W2,
                                     const float* __restrict__ a_src2,
                                     const float* __restrict__ a_dst2) {
    __shared__ float Ws[D1 * CLS + 64];
    __shared__ float as_sh[CLS], ad_sh[CLS];
    int tid = threadIdx.x;
    for (int i = tid; i < D1 * CLS + 64; i += blockDim.x)
        Ws[i] = (i < D1 * CLS) ? W2[i] : 0.f;
    if (tid < CLS) { as_sh[tid] = a_src2[tid]; ad_sh[tid] = a_dst2[tid]; }
    __syncthreads();

    int lane = tid & 31;
    int warpsPerBlock = blockDim.x >> 5;
    int gw = blockIdx.x * warpsPerBlock + (tid >> 5);
    int stride = gridDim.x * warpsPerBlock;

    for (int n = gw; n < NN; n += stride) {
        const float* xp = &g_hout1[(size_t)n * D1];
        float acc0a = 0.f, acc0b = 0.f, acc1a = 0.f, acc1b = 0.f;
#pragma unroll
        for (int kb = 0; kb < D1 / 32; kb++) {
            float xv = xp[kb * 32 + lane];
#pragma unroll
            for (int j = 0; j < 32; j += 2) {
                float xj0 = __shfl_sync(0xffffffffu, xv, j);
                float xj1 = __shfl_sync(0xffffffffu, xv, j + 1);
                int k0 = kb * 32 + j;
                acc0a = fmaf(xj0, Ws[k0 * CLS + lane], acc0a);
                acc1a = fmaf(xj0, Ws[k0 * CLS + 32 + lane], acc1a);
                acc0b = fmaf(xj1, Ws[(k0 + 1) * CLS + lane], acc0b);
                acc1b = fmaf(xj1, Ws[(k0 + 1) * CLS + 32 + lane], acc1b);
            }
        }
        float v0 = acc0a + acc0b;
        float v1 = acc1a + acc1b;
        g_h2lin[(size_t)n * CLSP + lane] = v0;
        if (lane < CLS - 32) g_h2lin[(size_t)n * CLSP + 32 + lane] = v1;
        float ps = v0 * as_sh[lane] + ((lane < CLS - 32) ? v1 * as_sh[32 + lane] : 0.f);
        float pd = v0 * ad_sh[lane] + ((lane < CLS - 32) ? v1 * ad_sh[32 + lane] : 0.f);
#pragma unroll
        for (int off = 16; off > 0; off >>= 1) {
            ps += __shfl_xor_sync(0xffffffffu, ps, off);
            pd += __shfl_xor_sync(0xffffffffu, pd, off);
        }
        if (lane == 0) { g_as2[n] = ps; g_ad2[n] = pd; }
    }
}

// ---------------- layer2 aggregation + log_softmax ----------------------------
__global__ void agg2_kernel(const float* __restrict__ b2, float* __restrict__ out) {
    int n = (blockIdx.x * blockDim.x + threadIdx.x) >> 5;
    int lane = threadIdx.x & 31;
    if (n >= NN) return;
    int st = g_starts[n];
    int d  = g_deg[n];
    float adn = g_ad2[n];

    float den = 0.f;
    for (int j = lane; j < d; j += 32) {
        int s = __ldg(&g_ssrc[st + j]);
        float e = __ldg(&g_as2[s]) + adn;
        e = fmaxf(e, 0.2f * e);
        float ex = __expf(e);
        g_wbuf2[st + j] = ex;
        den += ex;
    }
#pragma unroll
    for (int off = 16; off > 0; off >>= 1)
        den += __shfl_xor_sync(0xffffffffu, den, off);
    float inv = 1.f / (den + 1e-16f);

    float acc0 = 0.f, acc1 = 0.f;
#pragma unroll 4
    for (int j = 0; j < d; j++) {
        int s = __ldg(&g_ssrc[st + j]);
        float w = g_wbuf2[st + j] * inv;
        const float* hp = &g_h2lin[(size_t)s * CLSP];
        acc0 = fmaf(__ldg(&hp[lane]), w, acc0);
        if (lane < CLS - 32) acc1 = fmaf(__ldg(&hp[32 + lane]), w, acc1);
    }
    float v0 = acc0 + __ldg(&b2[lane]);
    float v1 = (lane < CLS - 32) ? (acc1 + __ldg(&b2[32 + lane])) : -CUDART_INF_F;

    float m = fmaxf(v0, v1);
#pragma unroll
    for (int off = 16; off > 0; off >>= 1)
        m = fmaxf(m, __shfl_xor_sync(0xffffffffu, m, off));
    float s0 = __expf(v0 - m) + ((lane < CLS - 32) ? __expf(v1 - m) : 0.f);
#pragma unroll
    for (int off = 16; off > 0; off >>= 1)
        s0 += __shfl_xor_sync(0xffffffffu, s0, off);
    float lse = m + logf(s0);

    out[(size_t)n * CLS + lane] = v0 - lse;
    if (lane < CLS - 32) out[(size_t)n * CLS + 32 + lane] = v1 - lse;
}

// ---------------- launch ------------------------------------------------------
extern "C" void kernel_launch(void* const* d_in, const int* in_sizes, int n_in,
                              void* d_out, int out_size) {
    const float* x      = (const float*)d_in[0];
    const int*   ei     = (const int*)d_in[1];
    const float* W1     = (const float*)d_in[2];
    const float* a_src1 = (const float*)d_in[3];
    const float* a_dst1 = (const float*)d_in[4];
    const float* b1     = (const float*)d_in[5];
    const float* W2     = (const float*)d_in[6];
    const float* a_src2 = (const float*)d_in[7];
    const float* a_dst2 = (const float*)d_in[8];
    const float* b2     = (const float*)d_in[9];
    float* out = (float*)d_out;

    const int nb_scan = (NN + 1023) / 1024;   // 49

    static cudaStream_t s2 = nullptr;
    static cudaEvent_t evFork = nullptr, evCSR = nullptr;
    if (s2 == nullptr) {
        cudaStreamCreateWithFlags(&s2, cudaStreamNonBlocking);
        cudaEventCreateWithFlags(&evFork, cudaEventDisableTiming);
        cudaEventCreateWithFlags(&evCSR, cudaEventDisableTiming);
    }

    // fork: CSR build chain on side stream, concurrent with prep+GEMM+alpha1
    cudaEventRecord(evFork, 0);
    cudaStreamWaitEvent(s2, evFork, 0);
    zero_deg_kernel<<<(NN + 255) / 256, 256, 0, s2>>>();
    hist_kernel<<<(E2 + 255) / 256, 256, 0, s2>>>(ei);
    scan_block_kernel<<<nb_scan, 1024, 0, s2>>>();
    scan_parts_kernel<<<1, 64, 0, s2>>>(nb_scan);
    finalize_scan_kernel<<<(NN + 255) / 256, 256, 0, s2>>>();
    fill_kernel<<<(E2 + 255) / 256, 256, 0, s2>>>(ei);
    cudaEventRecord(evCSR, s2);

    // main stream: prep, GEMM, alpha1
    prep_x_kernel<<<(NN * FIN / 4 + 255) / 256, 256>>>(x);
    prep_w_kernel<<<(D1 * (FIN / 2) + 255) / 256, 256>>>(W1);
    sgemm1_tc_kernel<<<dim3(2, (NN + 127) / 128), 256>>>();
    alpha1_kernel<<<(NN * 32 + 255) / 256, 256>>>(a_src1, a_dst1);

    // join: agg1 needs CSR + alpha1
    cudaStreamWaitEvent(0, evCSR, 0);
    agg1_kernel<<<(NN * 32 + 255) / 256, 256>>>(b1);

    // layer 2
    layer2_linear_kernel<<<592, 256>>>(W2, a_src2, a_dst2);
    agg2_kernel<<<(NN * 32 + 255) / 256, 256>>>(b2, out);
}

// round 13
// speedup vs baseline: 1.2053x; 1.0041x over previous
#include <cuda_runtime.h>
#include <cuda_bf16.h>
#include <math_constants.h>
#include <cstdint>

// Problem constants (fixed by the dataset)
#define NN   50000
#define EE   800000
#define E2   (EE + NN)      // edges + self loops = 850000
#define FIN  512
#define H1   8
#define C1   32
#define D1   (H1 * C1)      // 256
#define CLS  40
#define C2P  32              // h2b row: 32 uint32 (128B aligned), pairs 0..19 used

// ---------------- scratch (static device globals; no runtime alloc) ----------
__device__ float g_h1[NN * D1];          // layer1 linear output [N,256] fp32
__device__ uint32_t g_h1b[NN * (D1/2)];  // bf16x2-packed h1 for agg1 gather
__device__ float g_as1[NN * H1];
__device__ float g_ad1[NN * H1];
__device__ float g_hout1[NN * D1];       // elu(agg1 + b1) [N,256]
__device__ uint32_t g_h2b[NN * C2P];     // bf16x2-packed layer2 linear output
__device__ float g_as2[NN];
__device__ float g_ad2[NN];
__device__ float g_wbuf[E2 * H1];        // per-edge exp(logit), interleaved [edge][h]
__device__ float g_wbuf2[E2];
__device__ int   g_deg[NN];
__device__ int   g_incl[NN];
__device__ int   g_starts[NN];
__device__ int   g_cursor[NN];
__device__ int   g_ssrc[E2];
__device__ int   g_parts[64];
__device__ int   g_parts_ex[64];
// bf16 split-precision operands for GEMM1
__device__ uint32_t g_xhi[NN * (FIN / 2)];
__device__ uint32_t g_xlo[NN * (FIN / 2)];
__device__ uint32_t g_w1t_hi[D1 * (FIN / 2)];
__device__ uint32_t g_w1t_lo[D1 * (FIN / 2)];

// ---------------- bf16 split helpers -----------------------------------------
__device__ __forceinline__ void split2(float x, float y, uint32_t& hi, uint32_t& lo) {
    __nv_bfloat16 hx = __float2bfloat16_rn(x);
    __nv_bfloat16 hy = __float2bfloat16_rn(y);
    float lxf = x - __bfloat162float(hx);
    float lyf = y - __bfloat162float(hy);
    __nv_bfloat162 hv; hv.x = hx; hv.y = hy;
    __nv_bfloat162 lv = __floats2bfloat162_rn(lxf, lyf);
    hi = *reinterpret_cast<uint32_t*>(&hv);
    lo = *reinterpret_cast<uint32_t*>(&lv);
}

__global__ void prep_x_kernel(const float* __restrict__ x) {
    int i = blockIdx.x * blockDim.x + threadIdx.x;
    const int NQ = NN * FIN / 4;
    if (i >= NQ) return;
    float4 v = ((const float4*)x)[i];
    uint32_t h0, l0, h1, l1;
    split2(v.x, v.y, h0, l0);
    split2(v.z, v.w, h1, l1);
    g_xhi[2 * i]     = h0;  g_xhi[2 * i + 1] = h1;
    g_xlo[2 * i]     = l0;  g_xlo[2 * i + 1] = l1;
}

__global__ void prep_w_kernel(const float* __restrict__ W1) {
    int idx = blockIdx.x * blockDim.x + threadIdx.x;
    if (idx >= D1 * (FIN / 2)) return;
    int n = idx >> 8;
    int kp = idx & 255;
    float a = W1[(size_t)(2 * kp) * D1 + n];
    float b = W1[(size_t)(2 * kp + 1) * D1 + n];
    uint32_t hi, lo;
    split2(a, b, hi, lo);
    g_w1t_hi[idx] = hi;
    g_w1t_lo[idx] = lo;
}

// ---------------- tensor-core GEMM1 (R5/R10 config) ---------------------------
#define MMA_BF16(c, a0, a1, a2, a3, b0, b1)                                    \
    asm volatile(                                                              \
        "mma.sync.aligned.m16n8k16.row.col.f32.bf16.bf16.f32 "                 \
        "{%0,%1,%2,%3}, {%4,%5,%6,%7}, {%8,%9}, {%0,%1,%2,%3};\n"              \
        : "+f"(c[0]), "+f"(c[1]), "+f"(c[2]), "+f"(c[3])                       \
        : "r"(a0), "r"(a1), "r"(a2), "r"(a3), "r"(b0), "r"(b1))

__device__ __forceinline__ void ldm4(uint32_t* r, uint32_t saddr) {
    asm volatile("ldmatrix.sync.aligned.m8n8.x4.shared.b16 {%0,%1,%2,%3}, [%4];"
                 : "=r"(r[0]), "=r"(r[1]), "=r"(r[2]), "=r"(r[3]) : "r"(saddr));
}

__global__ void __launch_bounds__(256, 2) sgemm1_tc_kernel() {
    __shared__ uint32_t As_hi[2][128 * 8];
    __shared__ uint32_t As_lo[2][128 * 8];
    __shared__ uint32_t Bs_hi[2][128 * 8];
    __shared__ uint32_t Bs_lo[2][128 * 8];

    const int t = threadIdx.x, lane = t & 31, wid = t >> 5;
    const int warpM = wid >> 1, warpN = wid & 1;
    const int rowBase = blockIdx.y * 128, colBase = blockIdx.x * 128;

    const int lrow  = t >> 1;
    const int lhalf = t & 1;
    const int arow_g = rowBase + lrow;
    const bool avalid = arow_g < NN;
    const size_t a_base = (size_t)(avalid ? arow_g : 0) * (FIN / 2) + lhalf * 4;
    const size_t b_base = (size_t)(colBase + lrow) * (FIN / 2) + lhalf * 4;
    const int s_off = lrow * 8 + ((lhalf * 4) ^ (lrow & 4));

    const int lr = lane & 15, kq = lane >> 4;
    uint32_t off_a[2], off_b[4];
#pragma unroll
    for (int mt = 0; mt < 2; mt++) {
        int r = warpM * 32 + mt * 16 + lr;
        off_a[mt] = (uint32_t)(r * 8 + ((kq * 4) ^ (r & 4))) * 4u;
    }
#pragma unroll
    for (int np = 0; np < 4; np++) {
        int r = warpN * 64 + np * 16 + lr;
        off_b[np] = (uint32_t)(r * 8 + ((kq * 4) ^ (r & 4))) * 4u;
    }
    uint32_t baseAh[2], baseAl[2], baseBh[2], baseBl[2];
#pragma unroll
    for (int b = 0; b < 2; b++) {
        baseAh[b] = (uint32_t)__cvta_generic_to_shared(&As_hi[b][0]);
        baseAl[b] = (uint32_t)__cvta_generic_to_shared(&As_lo[b][0]);
        baseBh[b] = (uint32_t)__cvta_generic_to_shared(&Bs_hi[b][0]);
        baseBl[b] = (uint32_t)__cvta_generic_to_shared(&Bs_lo[b][0]);
    }

    float acc[2][8][4];
#pragma unroll
    for (int mt = 0; mt < 2; mt++)
#pragma unroll
        for (int nt = 0; nt < 8; nt++)
#pragma unroll
            for (int q = 0; q < 4; q++) acc[mt][nt][q] = 0.f;

    const uint4 z4 = make_uint4(0, 0, 0, 0);
    uint4 ra_h, ra_l, rb_h, rb_l;

    ra_h = avalid ? *(const uint4*)&g_xhi[a_base] : z4;
    ra_l = avalid ? *(const uint4*)&g_xlo[a_base] : z4;
    rb_h = *(const uint4*)&g_w1t_hi[b_base];
    rb_l = *(const uint4*)&g_w1t_lo[b_base];
    *(uint4*)&As_hi[0][s_off] = ra_h;
    *(uint4*)&As_lo[0][s_off] = ra_l;
    *(uint4*)&Bs_hi[0][s_off] = rb_h;
    *(uint4*)&Bs_lo[0][s_off] = rb_l;
    __syncthreads();

    const int NSTAGE = FIN / 16;    // 32
    for (int ks = 0; ks < NSTAGE; ks++) {
        const int cur = ks & 1;
        if (ks + 1 < NSTAGE) {
            size_t off = (size_t)(ks + 1) * 8;
            ra_h = avalid ? *(const uint4*)&g_xhi[a_base + off] : z4;
            ra_l = avalid ? *(const uint4*)&g_xlo[a_base + off] : z4;
            rb_h = *(const uint4*)&g_w1t_hi[b_base + off];
            rb_l = *(const uint4*)&g_w1t_lo[b_base + off];
        }

        uint32_t afh[2][4], afl[2][4];
        ldm4(afh[0], baseAh[cur] + off_a[0]);
        ldm4(afh[1], baseAh[cur] + off_a[1]);
        ldm4(afl[0], baseAl[cur] + off_a[0]);
        ldm4(afl[1], baseAl[cur] + off_a[1]);

#pragma unroll
        for (int np = 0; np < 4; np++) {
            uint32_t bh[4], bl[4];
            ldm4(bh, baseBh[cur] + off_b[np]);
            ldm4(bl, baseBl[cur] + off_b[np]);
#pragma unroll
            for (int mt = 0; mt < 2; mt++) {
                MMA_BF16(acc[mt][2 * np],     afh[mt][0], afh[mt][1], afh[mt][2], afh[mt][3], bh[0], bh[2]);
                MMA_BF16(acc[mt][2 * np],     afh[mt][0], afh[mt][1], afh[mt][2], afh[mt][3], bl[0], bl[2]);
                MMA_BF16(acc[mt][2 * np],     afl[mt][0], afl[mt][1], afl[mt][2], afl[mt][3], bh[0], bh[2]);
                MMA_BF16(acc[mt][2 * np + 1], afh[mt][0], afh[mt][1], afh[mt][2], afh[mt][3], bh[1], bh[3]);
                MMA_BF16(acc[mt][2 * np + 1], afh[mt][0], afh[mt][1], afh[mt][2], afh[mt][3], bl[1], bl[3]);
                MMA_BF16(acc[mt][2 * np + 1], afl[mt][0], afl[mt][1], afl[mt][2], afl[mt][3], bh[1], bh[3]);
            }
        }
        if (ks + 1 < NSTAGE) {
            const int nxt = 1 - cur;
            *(uint4*)&As_hi[nxt][s_off] = ra_h;
            *(uint4*)&As_lo[nxt][s_off] = ra_l;
            *(uint4*)&Bs_hi[nxt][s_off] = rb_h;
            *(uint4*)&Bs_lo[nxt][s_off] = rb_l;
            __syncthreads();
        }
    }

#pragma unroll
    for (int mt = 0; mt < 2; mt++) {
        const int r = rowBase + warpM * 32 + mt * 16 + (lane >> 2);
#pragma unroll
        for (int nt = 0; nt < 8; nt++) {
            const int c = colBase + warpN * 64 + nt * 8 + (lane & 3) * 2;
            if (r < NN) {
                *(float2*)&g_h1[(size_t)r * D1 + c] = make_float2(acc[mt][nt][0], acc[mt][nt][1]);
                __nv_bfloat162 bv = __floats2bfloat162_rn(acc[mt][nt][0], acc[mt][nt][1]);
                g_h1b[(size_t)r * (D1/2) + (c >> 1)] = *reinterpret_cast<uint32_t*>(&bv);
            }
            if (r + 8 < NN) {
                *(float2*)&g_h1[(size_t)(r + 8) * D1 + c] = make_float2(acc[mt][nt][2], acc[mt][nt][3]);
                __nv_bfloat162 bv = __floats2bfloat162_rn(acc[mt][nt][2], acc[mt][nt][3]);
                g_h1b[(size_t)(r + 8) * (D1/2) + (c >> 1)] = *reinterpret_cast<uint32_t*>(&bv);
            }
        }
    }
}

// ---------------- alpha1: per-node attention logits (warp per node) ----------
__global__ void alpha1_kernel(const float* __restrict__ a_src, const float* __restrict__ a_dst) {
    int gw = (blockIdx.x * blockDim.x + threadIdx.x) >> 5;
    int lane = threadIdx.x & 31;
    if (gw >= NN) return;
    const float* hp = &g_h1[(size_t)gw * D1];
#pragma unroll
    for (int h = 0; h < H1; h++) {
        float v = hp[h * 32 + lane];
        float s1 = v * __ldg(&a_src[h * 32 + lane]);
        float s2 = v * __ldg(&a_dst[h * 32 + lane]);
#pragma unroll
        for (int off = 16; off > 0; off >>= 1) {
            s1 += __shfl_xor_sync(0xffffffffu, s1, off);
            s2 += __shfl_xor_sync(0xffffffffu, s2, off);
        }
        if (lane == 0) {
            g_as1[gw * H1 + h] = s1;
            g_ad1[gw * H1 + h] = s2;
        }
    }
}

// ---------------- CSR build ---------------------------------------------------
__global__ void zero_deg_kernel() {
    int i = blockIdx.x * blockDim.x + threadIdx.x;
    if (i < NN) g_deg[i] = 0;
}

__global__ void hist_kernel(const int* __restrict__ ei) {
    int i = blockIdx.x * blockDim.x + threadIdx.x;
    if (i >= E2) return;
    int d = (i < EE) ? __ldg(&ei[EE + i]) : (i - EE);
    atomicAdd(&g_deg[d], 1);
}

__global__ void scan_block_kernel() {
    __shared__ int sh[1024];
    int tid = threadIdx.x;
    int i = blockIdx.x * 1024 + tid;
    int v = (i < NN) ? g_deg[i] : 0;
    sh[tid] = v;
    __syncthreads();
#pragma unroll
    for (int off = 1; off < 1024; off <<= 1) {
        int t = (tid >= off) ? sh[tid - off] : 0;
        __syncthreads();
        sh[tid] += t;
        __syncthreads();
    }
    if (i < NN) g_incl[i] = sh[tid];
    if (tid == 1023) g_parts[blockIdx.x] = sh[tid];
}

__global__ void scan_parts_kernel(int nb) {
    __shared__ int sh[64];
    int tid = threadIdx.x;
    int v = (tid < nb) ? g_parts[tid] : 0;
    sh[tid] = v;
    __syncthreads();
#pragma unroll
    for (int off = 1; off < 64; off <<= 1) {
        int t = (tid >= off) ? sh[tid - off] : 0;
        __syncthreads();
        sh[tid] += t;
        __syncthreads();
    }
    if (tid < nb) g_parts_ex[tid] = sh[tid] - v;
}

__global__ void finalize_scan_kernel() {
    int i = blockIdx.x * blockDim.x + threadIdx.x;
    if (i >= NN) return;
    int start = g_incl[i] - g_deg[i] + g_parts_ex[i >> 10];
    g_starts[i] = start;
    g_cursor[i] = start;
}

__global__ void fill_kernel(const int* __restrict__ ei) {
    int i = blockIdx.x * blockDim.x + threadIdx.x;
    if (i >= E2) return;
    int s, d;
    if (i < EE) { s = __ldg(&ei[i]); d = __ldg(&ei[EE + i]); }
    else        { s = i - EE; d = s; }
    int p = atomicAdd(&g_cursor[d], 1);
    g_ssrc[p] = s;
}

// ---------------- layer1 aggregation (warp per dst node, bf16 gather) ---------
__global__ void agg1_kernel(const float* __restrict__ b1) {
    int n = (blockIdx.x * blockDim.x + threadIdx.x) >> 5;
    int lane = threadIdx.x & 31;
    if (n >= NN) return;
    int st = g_starts[n];
    int d  = g_deg[n];

    float4 adv0 = *(const float4*)&g_ad1[n * H1];
    float4 adv1 = *(const float4*)&g_ad1[n * H1 + 4];

    // pass A: per-edge exp for all heads + denominators (vectorized as1 loads)
    float den[H1];
#pragma unroll
    for (int h = 0; h < H1; h++) den[h] = 0.f;
    for (int j = lane; j < d; j += 32) {
        int s = __ldg(&g_ssrc[st + j]);
        float* wp = &g_wbuf[(size_t)(st + j) * H1];
        const float4* ap = (const float4*)&g_as1[s * H1];
        float4 a0 = __ldg(ap), a1 = __ldg(ap + 1);
        float e[H1];
        e[0] = a0.x + adv0.x;  e[1] = a0.y + adv0.y;
        e[2] = a0.z + adv0.z;  e[3] = a0.w + adv0.w;
        e[4] = a1.x + adv1.x;  e[5] = a1.y + adv1.y;
        e[6] = a1.z + adv1.z;  e[7] = a1.w + adv1.w;
#pragma unroll
        for (int h = 0; h < H1; h++) {
            float ee = fmaxf(e[h], 0.2f * e[h]);
            float ex = __expf(ee);
            wp[h] = ex;
            den[h] += ex;
        }
    }
#pragma unroll
    for (int h = 0; h < H1; h++) {
#pragma unroll
        for (int off = 16; off > 0; off >>= 1)
            den[h] += __shfl_xor_sync(0xffffffffu, den[h], off);
    }
    float inv[H1];
#pragma unroll
    for (int h = 0; h < H1; h++) inv[h] = 1.f / (den[h] + 1e-16f);

    // per-lane head for each q: pair index p = 32q + lane, head = 2q + (lane>>4)
    float invq[4];
#pragma unroll
    for (int q = 0; q < 4; q++)
        invq[q] = (lane >= 16) ? inv[2 * q + 1] : inv[2 * q];
    const int hsel = lane >> 4;

    // pass B: bf16x2 gather — 512B per edge per warp
    float2 acc2[4];
#pragma unroll
    for (int q = 0; q < 4; q++) acc2[q] = make_float2(0.f, 0.f);
#pragma unroll 4
    for (int j = 0; j < d; j++) {
        int s = __ldg(&g_ssrc[st + j]);
        const float* wp = &g_wbuf[(size_t)(st + j) * H1];
        const uint32_t* hb = &g_h1b[(size_t)s * (D1/2)];
#pragma unroll
        for (int q = 0; q < 4; q++) {
            float w = wp[2 * q + hsel] * invq[q];
            uint32_t u = __ldg(&hb[32 * q + lane]);
            __nv_bfloat162 bv = *reinterpret_cast<__nv_bfloat162*>(&u);
            float2 f = __bfloat1622float2(bv);
            acc2[q].x = fmaf(f.x, w, acc2[q].x);
            acc2[q].y = fmaf(f.y, w, acc2[q].y);
        }
    }

#pragma unroll
    for (int q = 0; q < 4; q++) {
        int c0 = (32 * q + lane) * 2;
        float2 bb = *(const float2*)&b1[c0];
        float v0 = acc2[q].x + bb.x;
        float v1 = acc2[q].y + bb.y;
        v0 = (v0 > 0.f) ? v0 : expm1f(v0);
        v1 = (v1 > 0.f) ? v1 : expm1f(v1);
        *(float2*)&g_hout1[(size_t)n * D1 + c0] = make_float2(v0, v1);
    }
}

// ---------------- layer2 linear + alpha2 (bf16x2 packed output) ---------------
__global__ void layer2_linear_kernel(const float* __restrict__ W2,
                                     const float* __restrict__ a_src2,
                                     const float* __restrict__ a_dst2) {
    __shared__ float Ws[D1 * CLS + 64];
    __shared__ float as_sh[CLS], ad_sh[CLS];
    int tid = threadIdx.x;
    for (int i = tid; i < D1 * CLS + 64; i += blockDim.x)
        Ws[i] = (i < D1 * CLS) ? W2[i] : 0.f;
    if (tid < CLS) { as_sh[tid] = a_src2[tid]; ad_sh[tid] = a_dst2[tid]; }
    __syncthreads();

    int lane = tid & 31;
    int warpsPerBlock = blockDim.x >> 5;
    int gw = blockIdx.x * warpsPerBlock + (tid >> 5);
    int stride = gridDim.x * warpsPerBlock;

    for (int n = gw; n < NN; n += stride) {
        const float* xp = &g_hout1[(size_t)n * D1];
        float acc0a = 0.f, acc0b = 0.f, acc1a = 0.f, acc1b = 0.f;
#pragma unroll
        for (int kb = 0; kb < D1 / 32; kb++) {
            float xv = xp[kb * 32 + lane];
#pragma unroll
            for (int j = 0; j < 32; j += 2) {
                float xj0 = __shfl_sync(0xffffffffu, xv, j);
                float xj1 = __shfl_sync(0xffffffffu, xv, j + 1);
                int k0 = kb * 32 + j;
                acc0a = fmaf(xj0, Ws[k0 * CLS + lane], acc0a);
                acc1a = fmaf(xj0, Ws[k0 * CLS + 32 + lane], acc1a);
                acc0b = fmaf(xj1, Ws[(k0 + 1) * CLS + lane], acc0b);
                acc1b = fmaf(xj1, Ws[(k0 + 1) * CLS + 32 + lane], acc1b);
            }
        }
        float v0 = acc0a + acc0b;                          // channel lane (0..31)
        float v1 = acc1a + acc1b;                          // channel 32+lane (lane<8)

        // pack pairs to g_h2b: p<16 from v0, p=16..19 from v1
        float v0n = __shfl_down_sync(0xffffffffu, v0, 1);
        float v1n = __shfl_down_sync(0xffffffffu, v1, 1);
        if ((lane & 1) == 0) {
            __nv_bfloat162 bv = __floats2bfloat162_rn(v0, v0n);
            g_h2b[(size_t)n * C2P + (lane >> 1)] = *reinterpret_cast<uint32_t*>(&bv);
            if (lane < 8) {
                __nv_bfloat162 bw = __floats2bfloat162_rn(v1, v1n);
                g_h2b[(size_t)n * C2P + 16 + (lane >> 1)] = *reinterpret_cast<uint32_t*>(&bw);
            }
        }

        float ps = v0 * as_sh[lane] + ((lane < CLS - 32) ? v1 * as_sh[32 + lane] : 0.f);
        float pd = v0 * ad_sh[lane] + ((lane < CLS - 32) ? v1 * ad_sh[32 + lane] : 0.f);
#pragma unroll
        for (int off = 16; off > 0; off >>= 1) {
            ps += __shfl_xor_sync(0xffffffffu, ps, off);
            pd += __shfl_xor_sync(0xffffffffu, pd, off);
        }
        if (lane == 0) { g_as2[n] = ps; g_ad2[n] = pd; }
    }
}

// ---------------- layer2 aggregation + log_softmax (bf16 gather) --------------
__global__ void agg2_kernel(const float* __restrict__ b2, float* __restrict__ out) {
    int n = (blockIdx.x * blockDim.x + threadIdx.x) >> 5;
    int lane = threadIdx.x & 31;
    if (n >= NN) return;
    int st = g_starts[n];
    int d  = g_deg[n];
    float adn = g_ad2[n];

    float den = 0.f;
    for (int j = lane; j < d; j += 32) {
        int s = __ldg(&g_ssrc[st + j]);
        float e = __ldg(&g_as2[s]) + adn;
        e = fmaxf(e, 0.2f * e);
        float ex = __expf(e);
        g_wbuf2[st + j] = ex;
        den += ex;
    }
#pragma unroll
    for (int off = 16; off > 0; off >>= 1)
        den += __shfl_xor_sync(0xffffffffu, den, off);
    float inv = 1.f / (den + 1e-16f);

    // gather: lane p<20 holds channel pair (2p, 2p+1); 80B per edge
    float2 acc2 = make_float2(0.f, 0.f);
#pragma unroll 4
    for (int j = 0; j < d; j++) {
        int s = __ldg(&g_ssrc[st + j]);
        float w = g_wbuf2[st + j] * inv;
        if (lane < 20) {
            uint32_t u = __ldg(&g_h2b[(size_t)s * C2P + lane]);
            __nv_bfloat162 bv = *reinterpret_cast<__nv_bfloat162*>(&u);
            float2 f = __bfloat1622float2(bv);
            acc2.x = fmaf(f.x, w, acc2.x);
            acc2.y = fmaf(f.y, w, acc2.y);
        }
    }

    float2 vv = make_float2(-CUDART_INF_F, -CUDART_INF_F);
    if (lane < 20) {
        float2 bb = *(const float2*)&b2[2 * lane];
        vv.x = acc2.x + bb.x;
        vv.y = acc2.y + bb.y;
    }

    // log_softmax over 40 values held in pairs across lanes 0..19
    float m = fmaxf(vv.x, vv.y);
#pragma unroll
    for (int off = 16; off > 0; off >>= 1)
        m = fmaxf(m, __shfl_xor_sync(0xffffffffu, m, off));
    float s0 = (lane < 20) ? (__expf(vv.x - m) + __expf(vv.y - m)) : 0.f;
#pragma unroll
    for (int off = 16; off > 0; off >>= 1)
        s0 += __shfl_xor_sync(0xffffffffu, s0, off);
    float lse = m + logf(s0);

    if (lane < 20)
        *(float2*)&out[(size_t)n * CLS + 2 * lane] = make_float2(vv.x - lse, vv.y - lse);
}

// ---------------- launch ------------------------------------------------------
extern "C" void kernel_launch(void* const* d_in, const int* in_sizes, int n_in,
                              void* d_out, int out_size) {
    const float* x      = (const float*)d_in[0];
    const int*   ei     = (const int*)d_in[1];
    const float* W1     = (const float*)d_in[2];
    const float* a_src1 = (const float*)d_in[3];
    const float* a_dst1 = (const float*)d_in[4];
    const float* b1     = (const float*)d_in[5];
    const float* W2     = (const float*)d_in[6];
    const float* a_src2 = (const float*)d_in[7];
    const float* a_dst2 = (const float*)d_in[8];
    const float* b2     = (const float*)d_in[9];
    float* out = (float*)d_out;

    const int nb_scan = (NN + 1023) / 1024;   // 49

    static cudaStream_t s2 = nullptr;
    static cudaEvent_t evFork = nullptr, evCSR = nullptr;
    if (s2 == nullptr) {
        cudaStreamCreateWithFlags(&s2, cudaStreamNonBlocking);
        cudaEventCreateWithFlags(&evFork, cudaEventDisableTiming);
        cudaEventCreateWithFlags(&evCSR, cudaEventDisableTiming);
    }

    // fork: CSR build chain on side stream, concurrent with prep+GEMM+alpha1
    cudaEventRecord(evFork, 0);
    cudaStreamWaitEvent(s2, evFork, 0);
    zero_deg_kernel<<<(NN + 255) / 256, 256, 0, s2>>>();
    hist_kernel<<<(E2 + 255) / 256, 256, 0, s2>>>(ei);
    scan_block_kernel<<<nb_scan, 1024, 0, s2>>>();
    scan_parts_kernel<<<1, 64, 0, s2>>>(nb_scan);
    finalize_scan_kernel<<<(NN + 255) / 256, 256, 0, s2>>>();
    fill_kernel<<<(E2 + 255) / 256, 256, 0, s2>>>(ei);
    cudaEventRecord(evCSR, s2);

    // main stream: prep, GEMM, alpha1
    prep_x_kernel<<<(NN * FIN / 4 + 255) / 256, 256>>>(x);
    prep_w_kernel<<<(D1 * (FIN / 2) + 255) / 256, 256>>>(W1);
    sgemm1_tc_kernel<<<dim3(2, (NN + 127) / 128), 256>>>();
    alpha1_kernel<<<(NN * 32 + 255) / 256, 256>>>(a_src1, a_dst1);

    // join: agg1 needs CSR + alpha1
    cudaStreamWaitEvent(0, evCSR, 0);
    agg1_kernel<<<(NN * 32 + 255) / 256, 256>>>(b1);

    // layer 2
    layer2_linear_kernel<<<592, 256>>>(W2, a_src2, a_dst2);
    agg2_kernel<<<(NN * 32 + 255) / 256, 256>>>(b2, out);
}

// round 14
// speedup vs baseline: 1.3253x; 1.0996x over previous
#include <cuda_runtime.h>
#include <cuda_bf16.h>
#include <math_constants.h>
#include <cstdint>

// Problem constants (fixed by the dataset)
#define NN   50000
#define EE   800000
#define E2   (EE + NN)      // edges + self loops = 850000
#define FIN  512
#define H1   8
#define C1   32
#define D1   (H1 * C1)      // 256
#define CLS  40
#define C2P  32              // h2b row: 32 uint32 (128B aligned), pairs 0..19 used

// ---------------- scratch (static device globals; no runtime alloc) ----------
__device__ float g_h1[NN * D1];          // layer1 linear output [N,256] fp32
__device__ uint32_t g_h1b[NN * (D1/2)];  // bf16x2-packed h1 for agg1 gather
__device__ float g_as1[NN * H1];
__device__ float g_ad1[NN * H1];
__device__ float g_hout1[NN * D1];       // elu(agg1 + b1) [N,256]
__device__ uint32_t g_h2b[NN * C2P];     // bf16x2-packed layer2 linear output
__device__ float g_as2[NN];
__device__ float g_ad2[NN];
__device__ float g_wbuf[E2 * H1];        // per-edge exp(logit), interleaved [edge][h]
__device__ float g_wbuf2[E2];
__device__ int   g_deg[NN];
__device__ int   g_incl[NN];
__device__ int   g_starts[NN];
__device__ int   g_cursor[NN];
__device__ int   g_ssrc[E2];
__device__ int   g_parts[64];
__device__ int   g_parts_ex[64];
// bf16 split-precision W1 (x is split on the fly inside the GEMM)
__device__ uint32_t g_w1t_hi[D1 * (FIN / 2)];
__device__ uint32_t g_w1t_lo[D1 * (FIN / 2)];

// ---------------- bf16 split helpers -----------------------------------------
__device__ __forceinline__ void split2(float x, float y, uint32_t& hi, uint32_t& lo) {
    __nv_bfloat16 hx = __float2bfloat16_rn(x);
    __nv_bfloat16 hy = __float2bfloat16_rn(y);
    float lxf = x - __bfloat162float(hx);
    float lyf = y - __bfloat162float(hy);
    __nv_bfloat162 hv; hv.x = hx; hv.y = hy;
    __nv_bfloat162 lv = __floats2bfloat162_rn(lxf, lyf);
    hi = *reinterpret_cast<uint32_t*>(&hv);
    lo = *reinterpret_cast<uint32_t*>(&lv);
}

__global__ void prep_w_kernel(const float* __restrict__ W1) {
    int idx = blockIdx.x * blockDim.x + threadIdx.x;
    if (idx >= D1 * (FIN / 2)) return;
    int n = idx >> 8;
    int kp = idx & 255;
    float a = W1[(size_t)(2 * kp) * D1 + n];
    float b = W1[(size_t)(2 * kp + 1) * D1 + n];
    uint32_t hi, lo;
    split2(a, b, hi, lo);
    g_w1t_hi[idx] = hi;
    g_w1t_lo[idx] = lo;
}

// ---------------- tensor-core GEMM1 (fused x-split A path) --------------------
#define MMA_BF16(c, a0, a1, a2, a3, b0, b1)                                    \
    asm volatile(                                                              \
        "mma.sync.aligned.m16n8k16.row.col.f32.bf16.bf16.f32 "                 \
        "{%0,%1,%2,%3}, {%4,%5,%6,%7}, {%8,%9}, {%0,%1,%2,%3};\n"              \
        : "+f"(c[0]), "+f"(c[1]), "+f"(c[2]), "+f"(c[3])                       \
        : "r"(a0), "r"(a1), "r"(a2), "r"(a3), "r"(b0), "r"(b1))

__device__ __forceinline__ void ldm4(uint32_t* r, uint32_t saddr) {
    asm volatile("ldmatrix.sync.aligned.m8n8.x4.shared.b16 {%0,%1,%2,%3}, [%4];"
                 : "=r"(r[0]), "=r"(r[1]), "=r"(r[2]), "=r"(r[3]) : "r"(saddr));
}

__global__ void __launch_bounds__(256, 2) sgemm1_tc_kernel(const float* __restrict__ x) {
    __shared__ uint32_t As_hi[2][128 * 8];
    __shared__ uint32_t As_lo[2][128 * 8];
    __shared__ uint32_t Bs_hi[2][128 * 8];
    __shared__ uint32_t Bs_lo[2][128 * 8];

    const int t = threadIdx.x, lane = t & 31, wid = t >> 5;
    const int warpM = wid >> 1, warpN = wid & 1;
    const int rowBase = blockIdx.y * 128, colBase = blockIdx.x * 128;

    const int lrow  = t >> 1;
    const int lhalf = t & 1;
    const int arow_g = rowBase + lrow;
    const bool avalid = arow_g < NN;
    // x: fp32 row, this thread covers 8 k at offset lhalf*8 each stage
    const float* xrow = x + (size_t)(avalid ? arow_g : 0) * FIN + lhalf * 8;
    const size_t b_base = (size_t)(colBase + lrow) * (FIN / 2) + lhalf * 4;
    const int s_off = lrow * 8 + ((lhalf * 4) ^ (lrow & 4));

    const int lr = lane & 15, kq = lane >> 4;
    uint32_t off_a[2], off_b[4];
#pragma unroll
    for (int mt = 0; mt < 2; mt++) {
        int r = warpM * 32 + mt * 16 + lr;
        off_a[mt] = (uint32_t)(r * 8 + ((kq * 4) ^ (r & 4))) * 4u;
    }
#pragma unroll
    for (int np = 0; np < 4; np++) {
        int r = warpN * 64 + np * 16 + lr;
        off_b[np] = (uint32_t)(r * 8 + ((kq * 4) ^ (r & 4))) * 4u;
    }
    uint32_t baseAh[2], baseAl[2], baseBh[2], baseBl[2];
#pragma unroll
    for (int b = 0; b < 2; b++) {
        baseAh[b] = (uint32_t)__cvta_generic_to_shared(&As_hi[b][0]);
        baseAl[b] = (uint32_t)__cvta_generic_to_shared(&As_lo[b][0]);
        baseBh[b] = (uint32_t)__cvta_generic_to_shared(&Bs_hi[b][0]);
        baseBl[b] = (uint32_t)__cvta_generic_to_shared(&Bs_lo[b][0]);
    }

    float acc[2][8][4];
#pragma unroll
    for (int mt = 0; mt < 2; mt++)
#pragma unroll
        for (int nt = 0; nt < 8; nt++)
#pragma unroll
            for (int q = 0; q < 4; q++) acc[mt][nt][q] = 0.f;

    float4 xf0, xf1;
    uint4 rb_h, rb_l;

    auto split_store = [&](int buf, float4 f0, float4 f1) {
        uint4 hi, lo;
        split2(f0.x, f0.y, hi.x, lo.x);
        split2(f0.z, f0.w, hi.y, lo.y);
        split2(f1.x, f1.y, hi.z, lo.z);
        split2(f1.z, f1.w, hi.w, lo.w);
        *(uint4*)&As_hi[buf][s_off] = hi;
        *(uint4*)&As_lo[buf][s_off] = lo;
    };

    // prologue: stage 0
    xf0 = *(const float4*)&xrow[0];
    xf1 = *(const float4*)&xrow[4];
    rb_h = *(const uint4*)&g_w1t_hi[b_base];
    rb_l = *(const uint4*)&g_w1t_lo[b_base];
    split_store(0, xf0, xf1);
    *(uint4*)&Bs_hi[0][s_off] = rb_h;
    *(uint4*)&Bs_lo[0][s_off] = rb_l;
    __syncthreads();

    const int NSTAGE = FIN / 16;    // 32
    for (int ks = 0; ks < NSTAGE; ks++) {
        const int cur = ks & 1;
        if (ks + 1 < NSTAGE) {
            xf0 = *(const float4*)&xrow[(ks + 1) * 16];
            xf1 = *(const float4*)&xrow[(ks + 1) * 16 + 4];
            size_t off = (size_t)(ks + 1) * 8;
            rb_h = *(const uint4*)&g_w1t_hi[b_base + off];
            rb_l = *(const uint4*)&g_w1t_lo[b_base + off];
        }

        uint32_t afh[2][4], afl[2][4];
        ldm4(afh[0], baseAh[cur] + off_a[0]);
        ldm4(afh[1], baseAh[cur] + off_a[1]);
        ldm4(afl[0], baseAl[cur] + off_a[0]);
        ldm4(afl[1], baseAl[cur] + off_a[1]);

#pragma unroll
        for (int np = 0; np < 4; np++) {
            uint32_t bh[4], bl[4];
            ldm4(bh, baseBh[cur] + off_b[np]);
            ldm4(bl, baseBl[cur] + off_b[np]);
#pragma unroll
            for (int mt = 0; mt < 2; mt++) {
                MMA_BF16(acc[mt][2 * np],     afh[mt][0], afh[mt][1], afh[mt][2], afh[mt][3], bh[0], bh[2]);
                MMA_BF16(acc[mt][2 * np],     afh[mt][0], afh[mt][1], afh[mt][2], afh[mt][3], bl[0], bl[2]);
                MMA_BF16(acc[mt][2 * np],     afl[mt][0], afl[mt][1], afl[mt][2], afl[mt][3], bh[0], bh[2]);
                MMA_BF16(acc[mt][2 * np + 1], afh[mt][0], afh[mt][1], afh[mt][2], afh[mt][3], bh[1], bh[3]);
                MMA_BF16(acc[mt][2 * np + 1], afh[mt][0], afh[mt][1], afh[mt][2], afh[mt][3], bl[1], bl[3]);
                MMA_BF16(acc[mt][2 * np + 1], afl[mt][0], afl[mt][1], afl[mt][2], afl[mt][3], bh[1], bh[3]);
            }
        }
        if (ks + 1 < NSTAGE) {
            const int nxt = 1 - cur;
            split_store(nxt, xf0, xf1);
            *(uint4*)&Bs_hi[nxt][s_off] = rb_h;
            *(uint4*)&Bs_lo[nxt][s_off] = rb_l;
            __syncthreads();
        }
    }

#pragma unroll
    for (int mt = 0; mt < 2; mt++) {
        const int r = rowBase + warpM * 32 + mt * 16 + (lane >> 2);
#pragma unroll
        for (int nt = 0; nt < 8; nt++) {
            const int c = colBase + warpN * 64 + nt * 8 + (lane & 3) * 2;
            if (r < NN) {
                *(float2*)&g_h1[(size_t)r * D1 + c] = make_float2(acc[mt][nt][0], acc[mt][nt][1]);
                __nv_bfloat162 bv = __floats2bfloat162_rn(acc[mt][nt][0], acc[mt][nt][1]);
                g_h1b[(size_t)r * (D1/2) + (c >> 1)] = *reinterpret_cast<uint32_t*>(&bv);
            }
            if (r + 8 < NN) {
                *(float2*)&g_h1[(size_t)(r + 8) * D1 + c] = make_float2(acc[mt][nt][2], acc[mt][nt][3]);
                __nv_bfloat162 bv = __floats2bfloat162_rn(acc[mt][nt][2], acc[mt][nt][3]);
                g_h1b[(size_t)(r + 8) * (D1/2) + (c >> 1)] = *reinterpret_cast<uint32_t*>(&bv);
            }
        }
    }
}

// ---------------- alpha1: per-node attention logits (warp per node) ----------
__global__ void alpha1_kernel(const float* __restrict__ a_src, const float* __restrict__ a_dst) {
    int gw = (blockIdx.x * blockDim.x + threadIdx.x) >> 5;
    int lane = threadIdx.x & 31;
    if (gw >= NN) return;
    const float* hp = &g_h1[(size_t)gw * D1];
#pragma unroll
    for (int h = 0; h < H1; h++) {
        float v = hp[h * 32 + lane];
        float s1 = v * __ldg(&a_src[h * 32 + lane]);
        float s2 = v * __ldg(&a_dst[h * 32 + lane]);
#pragma unroll
        for (int off = 16; off > 0; off >>= 1) {
            s1 += __shfl_xor_sync(0xffffffffu, s1, off);
            s2 += __shfl_xor_sync(0xffffffffu, s2, off);
        }
        if (lane == 0) {
            g_as1[gw * H1 + h] = s1;
            g_ad1[gw * H1 + h] = s2;
        }
    }
}

// ---------------- CSR build ---------------------------------------------------
__global__ void zero_deg_kernel() {
    int i = blockIdx.x * blockDim.x + threadIdx.x;
    if (i < NN) g_deg[i] = 0;
}

__global__ void hist_kernel(const int* __restrict__ ei) {
    int i = blockIdx.x * blockDim.x + threadIdx.x;
    if (i >= E2) return;
    int d = (i < EE) ? __ldg(&ei[EE + i]) : (i - EE);
    atomicAdd(&g_deg[d], 1);
}

__global__ void scan_block_kernel() {
    __shared__ int sh[1024];
    int tid = threadIdx.x;
    int i = blockIdx.x * 1024 + tid;
    int v = (i < NN) ? g_deg[i] : 0;
    sh[tid] = v;
    __syncthreads();
#pragma unroll
    for (int off = 1; off < 1024; off <<= 1) {
        int t = (tid >= off) ? sh[tid - off] : 0;
        __syncthreads();
        sh[tid] += t;
        __syncthreads();
    }
    if (i < NN) g_incl[i] = sh[tid];
    if (tid == 1023) g_parts[blockIdx.x] = sh[tid];
}

__global__ void scan_parts_kernel(int nb) {
    __shared__ int sh[64];
    int tid = threadIdx.x;
    int v = (tid < nb) ? g_parts[tid] : 0;
    sh[tid] = v;
    __syncthreads();
#pragma unroll
    for (int off = 1; off < 64; off <<= 1) {
        int t = (tid >= off) ? sh[tid - off] : 0;
        __syncthreads();
        sh[tid] += t;
        __syncthreads();
    }
    if (tid < nb) g_parts_ex[tid] = sh[tid] - v;
}

__global__ void finalize_scan_kernel() {
    int i = blockIdx.x * blockDim.x + threadIdx.x;
    if (i >= NN) return;
    int start = g_incl[i] - g_deg[i] + g_parts_ex[i >> 10];
    g_starts[i] = start;
    g_cursor[i] = start;
}

__global__ void fill_kernel(const int* __restrict__ ei) {
    int i = blockIdx.x * blockDim.x + threadIdx.x;
    if (i >= E2) return;
    int s, d;
    if (i < EE) { s = __ldg(&ei[i]); d = __ldg(&ei[EE + i]); }
    else        { s = i - EE; d = s; }
    int p = atomicAdd(&g_cursor[d], 1);
    g_ssrc[p] = s;
}

// ---------------- layer1 aggregation (warp per dst node, bf16 gather) ---------
__global__ void agg1_kernel(const float* __restrict__ b1) {
    int n = (blockIdx.x * blockDim.x + threadIdx.x) >> 5;
    int lane = threadIdx.x & 31;
    if (n >= NN) return;
    int st = g_starts[n];
    int d  = g_deg[n];

    float4 adv0 = *(const float4*)&g_ad1[n * H1];
    float4 adv1 = *(const float4*)&g_ad1[n * H1 + 4];

    float den[H1];
#pragma unroll
    for (int h = 0; h < H1; h++) den[h] = 0.f;
    for (int j = lane; j < d; j += 32) {
        int s = __ldg(&g_ssrc[st + j]);
        float* wp = &g_wbuf[(size_t)(st + j) * H1];
        const float4* ap = (const float4*)&g_as1[s * H1];
        float4 a0 = __ldg(ap), a1 = __ldg(ap + 1);
        float e[H1];
        e[0] = a0.x + adv0.x;  e[1] = a0.y + adv0.y;
        e[2] = a0.z + adv0.z;  e[3] = a0.w + adv0.w;
        e[4] = a1.x + adv1.x;  e[5] = a1.y + adv1.y;
        e[6] = a1.z + adv1.z;  e[7] = a1.w + adv1.w;
#pragma unroll
        for (int h = 0; h < H1; h++) {
            float ee = fmaxf(e[h], 0.2f * e[h]);
            float ex = __expf(ee);
            wp[h] = ex;
            den[h] += ex;
        }
    }
#pragma unroll
    for (int h = 0; h < H1; h++) {
#pragma unroll
        for (int off = 16; off > 0; off >>= 1)
            den[h] += __shfl_xor_sync(0xffffffffu, den[h], off);
    }
    float inv[H1];
#pragma unroll
    for (int h = 0; h < H1; h++) inv[h] = 1.f / (den[h] + 1e-16f);

    float invq[4];
#pragma unroll
    for (int q = 0; q < 4; q++)
        invq[q] = (lane >= 16) ? inv[2 * q + 1] : inv[2 * q];
    const int hsel = lane >> 4;

    float2 acc2[4];
#pragma unroll
    for (int q = 0; q < 4; q++) acc2[q] = make_float2(0.f, 0.f);
#pragma unroll 4
    for (int j = 0; j < d; j++) {
        int s = __ldg(&g_ssrc[st + j]);
        const float* wp = &g_wbuf[(size_t)(st + j) * H1];
        const uint32_t* hb = &g_h1b[(size_t)s * (D1/2)];
#pragma unroll
        for (int q = 0; q < 4; q++) {
            float w = wp[2 * q + hsel] * invq[q];
            uint32_t u = __ldg(&hb[32 * q + lane]);
            __nv_bfloat162 bv = *reinterpret_cast<__nv_bfloat162*>(&u);
            float2 f = __bfloat1622float2(bv);
            acc2[q].x = fmaf(f.x, w, acc2[q].x);
            acc2[q].y = fmaf(f.y, w, acc2[q].y);
        }
    }

#pragma unroll
    for (int q = 0; q < 4; q++) {
        int c0 = (32 * q + lane) * 2;
        float2 bb = *(const float2*)&b1[c0];
        float v0 = acc2[q].x + bb.x;
        float v1 = acc2[q].y + bb.y;
        v0 = (v0 > 0.f) ? v0 : expm1f(v0);
        v1 = (v1 > 0.f) ? v1 : expm1f(v1);
        *(float2*)&g_hout1[(size_t)n * D1 + c0] = make_float2(v0, v1);
    }
}

// ---------------- layer2 linear + alpha2 (bf16x2 packed output) ---------------
__global__ void layer2_linear_kernel(const float* __restrict__ W2,
                                     const float* __restrict__ a_src2,
                                     const float* __restrict__ a_dst2) {
    __shared__ float Ws[D1 * CLS + 64];
    __shared__ float as_sh[CLS], ad_sh[CLS];
    int tid = threadIdx.x;
    for (int i = tid; i < D1 * CLS + 64; i += blockDim.x)
        Ws[i] = (i < D1 * CLS) ? W2[i] : 0.f;
    if (tid < CLS) { as_sh[tid] = a_src2[tid]; ad_sh[tid] = a_dst2[tid]; }
    __syncthreads();

    int lane = tid & 31;
    int warpsPerBlock = blockDim.x >> 5;
    int gw = blockIdx.x * warpsPerBlock + (tid >> 5);
    int stride = gridDim.x * warpsPerBlock;

    for (int n = gw; n < NN; n += stride) {
        const float* xp = &g_hout1[(size_t)n * D1];
        float acc0a = 0.f, acc0b = 0.f, acc1a = 0.f, acc1b = 0.f;
#pragma unroll
        for (int kb = 0; kb < D1 / 32; kb++) {
            float xv = xp[kb * 32 + lane];
#pragma unroll
            for (int j = 0; j < 32; j += 2) {
                float xj0 = __shfl_sync(0xffffffffu, xv, j);
                float xj1 = __shfl_sync(0xffffffffu, xv, j + 1);
                int k0 = kb * 32 + j;
                acc0a = fmaf(xj0, Ws[k0 * CLS + lane], acc0a);
                acc1a = fmaf(xj0, Ws[k0 * CLS + 32 + lane], acc1a);
                acc0b = fmaf(xj1, Ws[(k0 + 1) * CLS + lane], acc0b);
                acc1b = fmaf(xj1, Ws[(k0 + 1) * CLS + 32 + lane], acc1b);
            }
        }
        float v0 = acc0a + acc0b;
        float v1 = acc1a + acc1b;

        float v0n = __shfl_down_sync(0xffffffffu, v0, 1);
        float v1n = __shfl_down_sync(0xffffffffu, v1, 1);
        if ((lane & 1) == 0) {
            __nv_bfloat162 bv = __floats2bfloat162_rn(v0, v0n);
            g_h2b[(size_t)n * C2P + (lane >> 1)] = *reinterpret_cast<uint32_t*>(&bv);
            if (lane < 8) {
                __nv_bfloat162 bw = __floats2bfloat162_rn(v1, v1n);
                g_h2b[(size_t)n * C2P + 16 + (lane >> 1)] = *reinterpret_cast<uint32_t*>(&bw);
            }
        }

        float ps = v0 * as_sh[lane] + ((lane < CLS - 32) ? v1 * as_sh[32 + lane] : 0.f);
        float pd = v0 * ad_sh[lane] + ((lane < CLS - 32) ? v1 * ad_sh[32 + lane] : 0.f);
#pragma unroll
        for (int off = 16; off > 0; off >>= 1) {
            ps += __shfl_xor_sync(0xffffffffu, ps, off);
            pd += __shfl_xor_sync(0xffffffffu, pd, off);
        }
        if (lane == 0) { g_as2[n] = ps; g_ad2[n] = pd; }
    }
}

// ---------------- layer2 aggregation + log_softmax (bf16 gather) --------------
__global__ void agg2_kernel(const float* __restrict__ b2, float* __restrict__ out) {
    int n = (blockIdx.x * blockDim.x + threadIdx.x) >> 5;
    int lane = threadIdx.x & 31;
    if (n >= NN) return;
    int st = g_starts[n];
    int d  = g_deg[n];
    float adn = g_ad2[n];

    float den = 0.f;
    for (int j = lane; j < d; j += 32) {
        int s = __ldg(&g_ssrc[st + j]);
        float e = __ldg(&g_as2[s]) + adn;
        e = fmaxf(e, 0.2f * e);
        float ex = __expf(e);
        g_wbuf2[st + j] = ex;
        den += ex;
    }
#pragma unroll
    for (int off = 16; off > 0; off >>= 1)
        den += __shfl_xor_sync(0xffffffffu, den, off);
    float inv = 1.f / (den + 1e-16f);

    float2 acc2 = make_float2(0.f, 0.f);
#pragma unroll 4
    for (int j = 0; j < d; j++) {
        int s = __ldg(&g_ssrc[st + j]);
        float w = g_wbuf2[st + j] * inv;
        if (lane < 20) {
            uint32_t u = __ldg(&g_h2b[(size_t)s * C2P + lane]);
            __nv_bfloat162 bv = *reinterpret_cast<__nv_bfloat162*>(&u);
            float2 f = __bfloat1622float2(bv);
            acc2.x = fmaf(f.x, w, acc2.x);
            acc2.y = fmaf(f.y, w, acc2.y);
        }
    }

    float2 vv = make_float2(-CUDART_INF_F, -CUDART_INF_F);
    if (lane < 20) {
        float2 bb = *(const float2*)&b2[2 * lane];
        vv.x = acc2.x + bb.x;
        vv.y = acc2.y + bb.y;
    }

    float m = fmaxf(vv.x, vv.y);
#pragma unroll
    for (int off = 16; off > 0; off >>= 1)
        m = fmaxf(m, __shfl_xor_sync(0xffffffffu, m, off));
    float s0 = (lane < 20) ? (__expf(vv.x - m) + __expf(vv.y - m)) : 0.f;
#pragma unroll
    for (int off = 16; off > 0; off >>= 1)
        s0 += __shfl_xor_sync(0xffffffffu, s0, off);
    float lse = m + logf(s0);

    if (lane < 20)
        *(float2*)&out[(size_t)n * CLS + 2 * lane] = make_float2(vv.x - lse, vv.y - lse);
}

// ---------------- launch ------------------------------------------------------
extern "C" void kernel_launch(void* const* d_in, const int* in_sizes, int n_in,
                              void* d_out, int out_size) {
    const float* x      = (const float*)d_in[0];
    const int*   ei     = (const int*)d_in[1];
    const float* W1     = (const float*)d_in[2];
    const float* a_src1 = (const float*)d_in[3];
    const float* a_dst1 = (const float*)d_in[4];
    const float* b1     = (const float*)d_in[5];
    const float* W2     = (const float*)d_in[6];
    const float* a_src2 = (const float*)d_in[7];
    const float* a_dst2 = (const float*)d_in[8];
    const float* b2     = (const float*)d_in[9];
    float* out = (float*)d_out;

    const int nb_scan = (NN + 1023) / 1024;   // 49

    static cudaStream_t s2 = nullptr;
    static cudaEvent_t evFork = nullptr, evCSR = nullptr;
    if (s2 == nullptr) {
        cudaStreamCreateWithFlags(&s2, cudaStreamNonBlocking);
        cudaEventCreateWithFlags(&evFork, cudaEventDisableTiming);
        cudaEventCreateWithFlags(&evCSR, cudaEventDisableTiming);
    }

    // launch #1 (main): W1 split (tiny; GEMM depends on it in-stream)
    prep_w_kernel<<<(D1 * (FIN / 2) + 255) / 256, 256>>>(W1);

    // fork: CSR chain on side stream (launches #2-#5 here, rest after GEMM)
    cudaEventRecord(evFork, 0);
    cudaStreamWaitEvent(s2, evFork, 0);
    zero_deg_kernel<<<(NN + 255) / 256, 256, 0, s2>>>();          // #2
    hist_kernel<<<(E2 + 255) / 256, 256, 0, s2>>>(ei);            // #3
    scan_block_kernel<<<nb_scan, 1024, 0, s2>>>();                // #4
    scan_parts_kernel<<<1, 64, 0, s2>>>(nb_scan);                 // #5

    // launch #6 (main): GEMM — lands in the ncu -s 5 -c 1 capture window
    sgemm1_tc_kernel<<<dim3(2, (NN + 127) / 128), 256>>>(x);

    finalize_scan_kernel<<<(NN + 255) / 256, 256, 0, s2>>>();     // #7
    fill_kernel<<<(E2 + 255) / 256, 256, 0, s2>>>(ei);            // #8
    cudaEventRecord(evCSR, s2);

    alpha1_kernel<<<(NN * 32 + 255) / 256, 256>>>(a_src1, a_dst1);

    // join: agg1 needs CSR + alpha1
    cudaStreamWaitEvent(0, evCSR, 0);
    agg1_kernel<<<(NN * 32 + 255) / 256, 256>>>(b1);

    // layer 2
    layer2_linear_kernel<<<592, 256>>>(W2, a_src2, a_dst2);
    agg2_kernel<<<(NN * 32 + 255) / 256, 256>>>(b2, out);
}

// round 15
// speedup vs baseline: 1.5191x; 1.1462x over previous
#include <cuda_runtime.h>
#include <cuda_bf16.h>
#include <math_constants.h>
#include <cstdint>

// Problem constants (fixed by the dataset)
#define NN   50000
#define EE   800000
#define E2   (EE + NN)      // edges + self loops = 850000
#define FIN  512
#define H1   8
#define C1   32
#define D1   (H1 * C1)      // 256
#define CLS  40
#define C2P  32              // h2b row: 32 uint32 (128B aligned), pairs 0..19 used

// ---------------- scratch (static device globals; no runtime alloc) ----------
__device__ float g_h1[NN * D1];          // layer1 linear output [N,256] fp32
__device__ uint32_t g_h1b[NN * (D1/2)];  // bf16x2-packed h1 for agg1 gather
__device__ float g_as1[NN * H1];
__device__ float g_ad1[NN * H1];
__device__ float g_hout1[NN * D1];       // elu(agg1 + b1) [N,256]
__device__ uint32_t g_h2b[NN * C2P];     // bf16x2-packed layer2 linear output
__device__ float g_as2[NN];
__device__ float g_ad2[NN];
__device__ float g_wbuf[E2 * H1];        // per-edge exp(logit), interleaved [edge][h]
__device__ float g_wbuf2[E2];
__device__ int   g_deg[NN];
__device__ int   g_incl[NN];
__device__ int   g_starts[NN];
__device__ int   g_cursor[NN];
__device__ int   g_ssrc[E2];
__device__ int   g_parts[64];
__device__ int   g_parts_ex[64];
// bf16 W1 transposed (x is converted on the fly inside the GEMM)
__device__ uint32_t g_w1t[D1 * (FIN / 2)];

// ---------------- prep: W1 -> transposed packed bf16 --------------------------
__global__ void prep_w_kernel(const float* __restrict__ W1) {
    int idx = blockIdx.x * blockDim.x + threadIdx.x;
    if (idx >= D1 * (FIN / 2)) return;
    int n = idx >> 8;
    int kp = idx & 255;
    float a = W1[(size_t)(2 * kp) * D1 + n];
    float b = W1[(size_t)(2 * kp + 1) * D1 + n];
    __nv_bfloat162 bv = __floats2bfloat162_rn(a, b);
    g_w1t[idx] = *reinterpret_cast<uint32_t*>(&bv);
}

// ---------------- tensor-core GEMM1 (plain bf16, fused x-convert) -------------
#define MMA_BF16(c, a0, a1, a2, a3, b0, b1)                                    \
    asm volatile(                                                              \
        "mma.sync.aligned.m16n8k16.row.col.f32.bf16.bf16.f32 "                 \
        "{%0,%1,%2,%3}, {%4,%5,%6,%7}, {%8,%9}, {%0,%1,%2,%3};\n"              \
        : "+f"(c[0]), "+f"(c[1]), "+f"(c[2]), "+f"(c[3])                       \
        : "r"(a0), "r"(a1), "r"(a2), "r"(a3), "r"(b0), "r"(b1))

__device__ __forceinline__ void ldm4(uint32_t* r, uint32_t saddr) {
    asm volatile("ldmatrix.sync.aligned.m8n8.x4.shared.b16 {%0,%1,%2,%3}, [%4];"
                 : "=r"(r[0]), "=r"(r[1]), "=r"(r[2]), "=r"(r[3]) : "r"(saddr));
}

__global__ void __launch_bounds__(256, 2) sgemm1_tc_kernel(const float* __restrict__ x) {
    __shared__ uint32_t As[2][128 * 8];
    __shared__ uint32_t Bs[2][128 * 8];

    const int t = threadIdx.x, lane = t & 31, wid = t >> 5;
    const int warpM = wid >> 1, warpN = wid & 1;
    const int rowBase = blockIdx.y * 128, colBase = blockIdx.x * 128;

    const int lrow  = t >> 1;
    const int lhalf = t & 1;
    const int arow_g = rowBase + lrow;
    const bool avalid = arow_g < NN;
    const float* xrow = x + (size_t)(avalid ? arow_g : 0) * FIN + lhalf * 8;
    const size_t b_base = (size_t)(colBase + lrow) * (FIN / 2) + lhalf * 4;
    const int s_off = lrow * 8 + ((lhalf * 4) ^ (lrow & 4));

    const int lr = lane & 15, kq = lane >> 4;
    uint32_t off_a[2], off_b[4];
#pragma unroll
    for (int mt = 0; mt < 2; mt++) {
        int r = warpM * 32 + mt * 16 + lr;
        off_a[mt] = (uint32_t)(r * 8 + ((kq * 4) ^ (r & 4))) * 4u;
    }
#pragma unroll
    for (int np = 0; np < 4; np++) {
        int r = warpN * 64 + np * 16 + lr;
        off_b[np] = (uint32_t)(r * 8 + ((kq * 4) ^ (r & 4))) * 4u;
    }
    uint32_t baseA[2], baseB[2];
#pragma unroll
    for (int b = 0; b < 2; b++) {
        baseA[b] = (uint32_t)__cvta_generic_to_shared(&As[b][0]);
        baseB[b] = (uint32_t)__cvta_generic_to_shared(&Bs[b][0]);
    }

    float acc[2][8][4];
#pragma unroll
    for (int mt = 0; mt < 2; mt++)
#pragma unroll
        for (int nt = 0; nt < 8; nt++)
#pragma unroll
            for (int q = 0; q < 4; q++) acc[mt][nt][q] = 0.f;

    float4 xf0, xf1;
    uint4 rb;

    auto pack_store = [&](int buf, float4 f0, float4 f1) {
        uint4 hv;
        __nv_bfloat162 b0 = __floats2bfloat162_rn(f0.x, f0.y);
        __nv_bfloat162 b1 = __floats2bfloat162_rn(f0.z, f0.w);
        __nv_bfloat162 b2 = __floats2bfloat162_rn(f1.x, f1.y);
        __nv_bfloat162 b3 = __floats2bfloat162_rn(f1.z, f1.w);
        hv.x = *reinterpret_cast<uint32_t*>(&b0);
        hv.y = *reinterpret_cast<uint32_t*>(&b1);
        hv.z = *reinterpret_cast<uint32_t*>(&b2);
        hv.w = *reinterpret_cast<uint32_t*>(&b3);
        *(uint4*)&As[buf][s_off] = hv;
    };

    // prologue: stage 0
    xf0 = *(const float4*)&xrow[0];
    xf1 = *(const float4*)&xrow[4];
    rb  = *(const uint4*)&g_w1t[b_base];
    pack_store(0, xf0, xf1);
    *(uint4*)&Bs[0][s_off] = rb;
    __syncthreads();

    const int NSTAGE = FIN / 16;    // 32
    for (int ks = 0; ks < NSTAGE; ks++) {
        const int cur = ks & 1;
        if (ks + 1 < NSTAGE) {
            xf0 = *(const float4*)&xrow[(ks + 1) * 16];
            xf1 = *(const float4*)&xrow[(ks + 1) * 16 + 4];
            rb  = *(const uint4*)&g_w1t[b_base + (size_t)(ks + 1) * 8];
        }

        uint32_t af[2][4];
        ldm4(af[0], baseA[cur] + off_a[0]);
        ldm4(af[1], baseA[cur] + off_a[1]);

#pragma unroll
        for (int np = 0; np < 4; np++) {
            uint32_t bh[4];
            ldm4(bh, baseB[cur] + off_b[np]);
#pragma unroll
            for (int mt = 0; mt < 2; mt++) {
                MMA_BF16(acc[mt][2 * np],     af[mt][0], af[mt][1], af[mt][2], af[mt][3], bh[0], bh[2]);
                MMA_BF16(acc[mt][2 * np + 1], af[mt][0], af[mt][1], af[mt][2], af[mt][3], bh[1], bh[3]);
            }
        }
        if (ks + 1 < NSTAGE) {
            const int nxt = 1 - cur;
            pack_store(nxt, xf0, xf1);
            *(uint4*)&Bs[nxt][s_off] = rb;
            __syncthreads();
        }
    }

#pragma unroll
    for (int mt = 0; mt < 2; mt++) {
        const int r = rowBase + warpM * 32 + mt * 16 + (lane >> 2);
#pragma unroll
        for (int nt = 0; nt < 8; nt++) {
            const int c = colBase + warpN * 64 + nt * 8 + (lane & 3) * 2;
            if (r < NN) {
                *(float2*)&g_h1[(size_t)r * D1 + c] = make_float2(acc[mt][nt][0], acc[mt][nt][1]);
                __nv_bfloat162 bv = __floats2bfloat162_rn(acc[mt][nt][0], acc[mt][nt][1]);
                g_h1b[(size_t)r * (D1/2) + (c >> 1)] = *reinterpret_cast<uint32_t*>(&bv);
            }
            if (r + 8 < NN) {
                *(float2*)&g_h1[(size_t)(r + 8) * D1 + c] = make_float2(acc[mt][nt][2], acc[mt][nt][3]);
                __nv_bfloat162 bv = __floats2bfloat162_rn(acc[mt][nt][2], acc[mt][nt][3]);
                g_h1b[(size_t)(r + 8) * (D1/2) + (c >> 1)] = *reinterpret_cast<uint32_t*>(&bv);
            }
        }
    }
}

// ---------------- alpha1: per-node attention logits (warp per node) ----------
__global__ void alpha1_kernel(const float* __restrict__ a_src, const float* __restrict__ a_dst) {
    int gw = (blockIdx.x * blockDim.x + threadIdx.x) >> 5;
    int lane = threadIdx.x & 31;
    if (gw >= NN) return;
    const float* hp = &g_h1[(size_t)gw * D1];
#pragma unroll
    for (int h = 0; h < H1; h++) {
        float v = hp[h * 32 + lane];
        float s1 = v * __ldg(&a_src[h * 32 + lane]);
        float s2 = v * __ldg(&a_dst[h * 32 + lane]);
#pragma unroll
        for (int off = 16; off > 0; off >>= 1) {
            s1 += __shfl_xor_sync(0xffffffffu, s1, off);
            s2 += __shfl_xor_sync(0xffffffffu, s2, off);
        }
        if (lane == 0) {
            g_as1[gw * H1 + h] = s1;
            g_ad1[gw * H1 + h] = s2;
        }
    }
}

// ---------------- CSR build ---------------------------------------------------
__global__ void zero_deg_kernel() {
    int i = blockIdx.x * blockDim.x + threadIdx.x;
    if (i < NN) g_deg[i] = 0;
}

__global__ void hist_kernel(const int* __restrict__ ei) {
    int i = blockIdx.x * blockDim.x + threadIdx.x;
    if (i >= E2) return;
    int d = (i < EE) ? __ldg(&ei[EE + i]) : (i - EE);
    atomicAdd(&g_deg[d], 1);
}

__global__ void scan_block_kernel() {
    __shared__ int sh[1024];
    int tid = threadIdx.x;
    int i = blockIdx.x * 1024 + tid;
    int v = (i < NN) ? g_deg[i] : 0;
    sh[tid] = v;
    __syncthreads();
#pragma unroll
    for (int off = 1; off < 1024; off <<= 1) {
        int t = (tid >= off) ? sh[tid - off] : 0;
        __syncthreads();
        sh[tid] += t;
        __syncthreads();
    }
    if (i < NN) g_incl[i] = sh[tid];
    if (tid == 1023) g_parts[blockIdx.x] = sh[tid];
}

__global__ void scan_parts_kernel(int nb) {
    __shared__ int sh[64];
    int tid = threadIdx.x;
    int v = (tid < nb) ? g_parts[tid] : 0;
    sh[tid] = v;
    __syncthreads();
#pragma unroll
    for (int off = 1; off < 64; off <<= 1) {
        int t = (tid >= off) ? sh[tid - off] : 0;
        __syncthreads();
        sh[tid] += t;
        __syncthreads();
    }
    if (tid < nb) g_parts_ex[tid] = sh[tid] - v;
}

__global__ void finalize_scan_kernel() {
    int i = blockIdx.x * blockDim.x + threadIdx.x;
    if (i >= NN) return;
    int start = g_incl[i] - g_deg[i] + g_parts_ex[i >> 10];
    g_starts[i] = start;
    g_cursor[i] = start;
}

__global__ void fill_kernel(const int* __restrict__ ei) {
    int i = blockIdx.x * blockDim.x + threadIdx.x;
    if (i >= E2) return;
    int s, d;
    if (i < EE) { s = __ldg(&ei[i]); d = __ldg(&ei[EE + i]); }
    else        { s = i - EE; d = s; }
    int p = atomicAdd(&g_cursor[d], 1);
    g_ssrc[p] = s;
}

// ---------------- layer1 aggregation (warp per dst node, bf16 gather) ---------
__global__ void agg1_kernel(const float* __restrict__ b1) {
    int n = (blockIdx.x * blockDim.x + threadIdx.x) >> 5;
    int lane = threadIdx.x & 31;
    if (n >= NN) return;
    int st = g_starts[n];
    int d  = g_deg[n];

    float4 adv0 = *(const float4*)&g_ad1[n * H1];
    float4 adv1 = *(const float4*)&g_ad1[n * H1 + 4];

    float den[H1];
#pragma unroll
    for (int h = 0; h < H1; h++) den[h] = 0.f;
    for (int j = lane; j < d; j += 32) {
        int s = __ldg(&g_ssrc[st + j]);
        float* wp = &g_wbuf[(size_t)(st + j) * H1];
        const float4* ap = (const float4*)&g_as1[s * H1];
        float4 a0 = __ldg(ap), a1 = __ldg(ap + 1);
        float e[H1];
        e[0] = a0.x + adv0.x;  e[1] = a0.y + adv0.y;
        e[2] = a0.z + adv0.z;  e[3] = a0.w + adv0.w;
        e[4] = a1.x + adv1.x;  e[5] = a1.y + adv1.y;
        e[6] = a1.z + adv1.z;  e[7] = a1.w + adv1.w;
#pragma unroll
        for (int h = 0; h < H1; h++) {
            float ee = fmaxf(e[h], 0.2f * e[h]);
            float ex = __expf(ee);
            wp[h] = ex;
            den[h] += ex;
        }
    }
#pragma unroll
    for (int h = 0; h < H1; h++) {
#pragma unroll
        for (int off = 16; off > 0; off >>= 1)
            den[h] += __shfl_xor_sync(0xffffffffu, den[h], off);
    }
    float inv[H1];
#pragma unroll
    for (int h = 0; h < H1; h++) inv[h] = 1.f / (den[h] + 1e-16f);

    float invq[4];
#pragma unroll
    for (int q = 0; q < 4; q++)
        invq[q] = (lane >= 16) ? inv[2 * q + 1] : inv[2 * q];
    const int hsel = lane >> 4;

    float2 acc2[4];
#pragma unroll
    for (int q = 0; q < 4; q++) acc2[q] = make_float2(0.f, 0.f);
#pragma unroll 4
    for (int j = 0; j < d; j++) {
        int s = __ldg(&g_ssrc[st + j]);
        const float* wp = &g_wbuf[(size_t)(st + j) * H1];
        const uint32_t* hb = &g_h1b[(size_t)s * (D1/2)];
#pragma unroll
        for (int q = 0; q < 4; q++) {
            float w = wp[2 * q + hsel] * invq[q];
            uint32_t u = __ldg(&hb[32 * q + lane]);
            __nv_bfloat162 bv = *reinterpret_cast<__nv_bfloat162*>(&u);
            float2 f = __bfloat1622float2(bv);
            acc2[q].x = fmaf(f.x, w, acc2[q].x);
            acc2[q].y = fmaf(f.y, w, acc2[q].y);
        }
    }

#pragma unroll
    for (int q = 0; q < 4; q++) {
        int c0 = (32 * q + lane) * 2;
        float2 bb = *(const float2*)&b1[c0];
        float v0 = acc2[q].x + bb.x;
        float v1 = acc2[q].y + bb.y;
        v0 = (v0 > 0.f) ? v0 : expm1f(v0);
        v1 = (v1 > 0.f) ? v1 : expm1f(v1);
        *(float2*)&g_hout1[(size_t)n * D1 + c0] = make_float2(v0, v1);
    }
}

// ---------------- layer2 linear + alpha2 (bf16x2 packed output) ---------------
__global__ void layer2_linear_kernel(const float* __restrict__ W2,
                                     const float* __restrict__ a_src2,
                                     const float* __restrict__ a_dst2) {
    __shared__ float Ws[D1 * CLS + 64];
    __shared__ float as_sh[CLS], ad_sh[CLS];
    int tid = threadIdx.x;
    for (int i = tid; i < D1 * CLS + 64; i += blockDim.x)
        Ws[i] = (i < D1 * CLS) ? W2[i] : 0.f;
    if (tid < CLS) { as_sh[tid] = a_src2[tid]; ad_sh[tid] = a_dst2[tid]; }
    __syncthreads();

    int lane = tid & 31;
    int warpsPerBlock = blockDim.x >> 5;
    int gw = blockIdx.x * warpsPerBlock + (tid >> 5);
    int stride = gridDim.x * warpsPerBlock;

    for (int n = gw; n < NN; n += stride) {
        const float* xp = &g_hout1[(size_t)n * D1];
        float acc0a = 0.f, acc0b = 0.f, acc1a = 0.f, acc1b = 0.f;
#pragma unroll
        for (int kb = 0; kb < D1 / 32; kb++) {
            float xv = xp[kb * 32 + lane];
#pragma unroll
            for (int j = 0; j < 32; j += 2) {
                float xj0 = __shfl_sync(0xffffffffu, xv, j);
                float xj1 = __shfl_sync(0xffffffffu, xv, j + 1);
                int k0 = kb * 32 + j;
                acc0a = fmaf(xj0, Ws[k0 * CLS + lane], acc0a);
                acc1a = fmaf(xj0, Ws[k0 * CLS + 32 + lane], acc1a);
                acc0b = fmaf(xj1, Ws[(k0 + 1) * CLS + lane], acc0b);
                acc1b = fmaf(xj1, Ws[(k0 + 1) * CLS + 32 + lane], acc1b);
            }
        }
        float v0 = acc0a + acc0b;
        float v1 = acc1a + acc1b;

        float v0n = __shfl_down_sync(0xffffffffu, v0, 1);
        float v1n = __shfl_down_sync(0xffffffffu, v1, 1);
        if ((lane & 1) == 0) {
            __nv_bfloat162 bv = __floats2bfloat162_rn(v0, v0n);
            g_h2b[(size_t)n * C2P + (lane >> 1)] = *reinterpret_cast<uint32_t*>(&bv);
            if (lane < 8) {
                __nv_bfloat162 bw = __floats2bfloat162_rn(v1, v1n);
                g_h2b[(size_t)n * C2P + 16 + (lane >> 1)] = *reinterpret_cast<uint32_t*>(&bw);
            }
        }

        float ps = v0 * as_sh[lane] + ((lane < CLS - 32) ? v1 * as_sh[32 + lane] : 0.f);
        float pd = v0 * ad_sh[lane] + ((lane < CLS - 32) ? v1 * ad_sh[32 + lane] : 0.f);
#pragma unroll
        for (int off = 16; off > 0; off >>= 1) {
            ps += __shfl_xor_sync(0xffffffffu, ps, off);
            pd += __shfl_xor_sync(0xffffffffu, pd, off);
        }
        if (lane == 0) { g_as2[n] = ps; g_ad2[n] = pd; }
    }
}

// ---------------- layer2 aggregation + log_softmax (bf16 gather) --------------
__global__ void agg2_kernel(const float* __restrict__ b2, float* __restrict__ out) {
    int n = (blockIdx.x * blockDim.x + threadIdx.x) >> 5;
    int lane = threadIdx.x & 31;
    if (n >= NN) return;
    int st = g_starts[n];
    int d  = g_deg[n];
    float adn = g_ad2[n];

    float den = 0.f;
    for (int j = lane; j < d; j += 32) {
        int s = __ldg(&g_ssrc[st + j]);
        float e = __ldg(&g_as2[s]) + adn;
        e = fmaxf(e, 0.2f * e);
        float ex = __expf(e);
        g_wbuf2[st + j] = ex;
        den += ex;
    }
#pragma unroll
    for (int off = 16; off > 0; off >>= 1)
        den += __shfl_xor_sync(0xffffffffu, den, off);
    float inv = 1.f / (den + 1e-16f);

    float2 acc2 = make_float2(0.f, 0.f);
#pragma unroll 4
    for (int j = 0; j < d; j++) {
        int s = __ldg(&g_ssrc[st + j]);
        float w = g_wbuf2[st + j] * inv;
        if (lane < 20) {
            uint32_t u = __ldg(&g_h2b[(size_t)s * C2P + lane]);
            __nv_bfloat162 bv = *reinterpret_cast<__nv_bfloat162*>(&u);
            float2 f = __bfloat1622float2(bv);
            acc2.x = fmaf(f.x, w, acc2.x);
            acc2.y = fmaf(f.y, w, acc2.y);
        }
    }

    float2 vv = make_float2(-CUDART_INF_F, -CUDART_INF_F);
    if (lane < 20) {
        float2 bb = *(const float2*)&b2[2 * lane];
        vv.x = acc2.x + bb.x;
        vv.y = acc2.y + bb.y;
    }

    float m = fmaxf(vv.x, vv.y);
#pragma unroll
    for (int off = 16; off > 0; off >>= 1)
        m = fmaxf(m, __shfl_xor_sync(0xffffffffu, m, off));
    float s0 = (lane < 20) ? (__expf(vv.x - m) + __expf(vv.y - m)) : 0.f;
#pragma unroll
    for (int off = 16; off > 0; off >>= 1)
        s0 += __shfl_xor_sync(0xffffffffu, s0, off);
    float lse = m + logf(s0);

    if (lane < 20)
        *(float2*)&out[(size_t)n * CLS + 2 * lane] = make_float2(vv.x - lse, vv.y - lse);
}

// ---------------- launch ------------------------------------------------------
extern "C" void kernel_launch(void* const* d_in, const int* in_sizes, int n_in,
                              void* d_out, int out_size) {
    const float* x      = (const float*)d_in[0];
    const int*   ei     = (const int*)d_in[1];
    const float* W1     = (const float*)d_in[2];
    const float* a_src1 = (const float*)d_in[3];
    const float* a_dst1 = (const float*)d_in[4];
    const float* b1     = (const float*)d_in[5];
    const float* W2     = (const float*)d_in[6];
    const float* a_src2 = (const float*)d_in[7];
    const float* a_dst2 = (const float*)d_in[8];
    const float* b2     = (const float*)d_in[9];
    float* out = (float*)d_out;

    const int nb_scan = (NN + 1023) / 1024;   // 49

    static cudaStream_t s2 = nullptr;
    static cudaEvent_t evFork = nullptr, evCSR = nullptr;
    if (s2 == nullptr) {
        cudaStreamCreateWithFlags(&s2, cudaStreamNonBlocking);
        cudaEventCreateWithFlags(&evFork, cudaEventDisableTiming);
        cudaEventCreateWithFlags(&evCSR, cudaEventDisableTiming);
    }

    // launch #1 (main): W1 pack (tiny; GEMM depends on it in-stream)
    prep_w_kernel<<<(D1 * (FIN / 2) + 255) / 256, 256>>>(W1);

    // fork: CSR chain on side stream
    cudaEventRecord(evFork, 0);
    cudaStreamWaitEvent(s2, evFork, 0);
    zero_deg_kernel<<<(NN + 255) / 256, 256, 0, s2>>>();
    hist_kernel<<<(E2 + 255) / 256, 256, 0, s2>>>(ei);
    scan_block_kernel<<<nb_scan, 1024, 0, s2>>>();
    scan_parts_kernel<<<1, 64, 0, s2>>>(nb_scan);

    // launch #6 (main): GEMM — in the ncu -s 5 -c 1 capture window
    sgemm1_tc_kernel<<<dim3(2, (NN + 127) / 128), 256>>>(x);

    finalize_scan_kernel<<<(NN + 255) / 256, 256, 0, s2>>>();
    fill_kernel<<<(E2 + 255) / 256, 256, 0, s2>>>(ei);
    cudaEventRecord(evCSR, s2);

    alpha1_kernel<<<(NN * 32 + 255) / 256, 256>>>(a_src1, a_dst1);

    // join: agg1 needs CSR + alpha1
    cudaStreamWaitEvent(0, evCSR, 0);
    agg1_kernel<<<(NN * 32 + 255) / 256, 256>>>(b1);

    // layer 2
    layer2_linear_kernel<<<592, 256>>>(W2, a_src2, a_dst2);
    agg2_kernel<<<(NN * 32 + 255) / 256, 256>>>(b2, out);
}

// round 16
// speedup vs baseline: 1.6691x; 1.0988x over previous
#include <cuda_runtime.h>
#include <cuda_bf16.h>
#include <math_constants.h>
#include <cstdint>

// Problem constants (fixed by the dataset)
#define NN   50000
#define EE   800000
#define E2   (EE + NN)      // edges + self loops = 850000
#define FIN  512
#define H1   8
#define C1   32
#define D1   (H1 * C1)      // 256
#define CLS  40
#define C2P  32              // h2b row: 32 uint32 (128B aligned), pairs 0..19 used

// ---------------- scratch (static device globals; no runtime alloc) ----------
__device__ uint32_t g_h1b[NN * (D1/2)];  // bf16x2-packed h1 (sole h1 representation)
__device__ float g_as1[NN * H1];
__device__ float g_ad1[NN * H1];
__device__ float g_hout1[NN * D1];       // elu(agg1 + b1) [N,256]
__device__ uint32_t g_h2b[NN * C2P];     // bf16x2-packed layer2 linear output
__device__ float g_as2[NN];
__device__ float g_ad2[NN];
__device__ float g_wbuf[E2 * H1];        // per-edge exp(logit), interleaved [edge][h]
__device__ float g_wbuf2[E2];
__device__ int   g_deg[NN];
__device__ int   g_incl[NN];
__device__ int   g_starts[NN];
__device__ int   g_cursor[NN];
__device__ int   g_ssrc[E2];
__device__ int   g_parts[64];
__device__ int   g_parts_ex[64];
// bf16 W1 transposed (x is converted on the fly inside the GEMM)
__device__ uint32_t g_w1t[D1 * (FIN / 2)];

// ---------------- prep: W1 -> transposed packed bf16 --------------------------
__global__ void prep_w_kernel(const float* __restrict__ W1) {
    int idx = blockIdx.x * blockDim.x + threadIdx.x;
    if (idx >= D1 * (FIN / 2)) return;
    int n = idx >> 8;
    int kp = idx & 255;
    float a = W1[(size_t)(2 * kp) * D1 + n];
    float b = W1[(size_t)(2 * kp + 1) * D1 + n];
    __nv_bfloat162 bv = __floats2bfloat162_rn(a, b);
    g_w1t[idx] = *reinterpret_cast<uint32_t*>(&bv);
}

// ---------------- tensor-core GEMM1 (bf16, fused x-convert + fused alpha1) ----
#define MMA_BF16(c, a0, a1, a2, a3, b0, b1)                                    \
    asm volatile(                                                              \
        "mma.sync.aligned.m16n8k16.row.col.f32.bf16.bf16.f32 "                 \
        "{%0,%1,%2,%3}, {%4,%5,%6,%7}, {%8,%9}, {%0,%1,%2,%3};\n"              \
        : "+f"(c[0]), "+f"(c[1]), "+f"(c[2]), "+f"(c[3])                       \
        : "r"(a0), "r"(a1), "r"(a2), "r"(a3), "r"(b0), "r"(b1))

__device__ __forceinline__ void ldm4(uint32_t* r, uint32_t saddr) {
    asm volatile("ldmatrix.sync.aligned.m8n8.x4.shared.b16 {%0,%1,%2,%3}, [%4];"
                 : "=r"(r[0]), "=r"(r[1]), "=r"(r[2]), "=r"(r[3]) : "r"(saddr));
}

__global__ void __launch_bounds__(256, 2) sgemm1_tc_kernel(const float* __restrict__ x,
                                                           const float* __restrict__ a_src1,
                                                           const float* __restrict__ a_dst1) {
    __shared__ uint32_t As[2][128 * 8];
    __shared__ uint32_t Bs[2][128 * 8];

    const int t = threadIdx.x, lane = t & 31, wid = t >> 5;
    const int warpM = wid >> 1, warpN = wid & 1;
    const int rowBase = blockIdx.y * 128, colBase = blockIdx.x * 128;

    const int lrow  = t >> 1;
    const int lhalf = t & 1;
    const int arow_g = rowBase + lrow;
    const bool avalid = arow_g < NN;
    const float* xrow = x + (size_t)(avalid ? arow_g : 0) * FIN + lhalf * 8;
    const size_t b_base = (size_t)(colBase + lrow) * (FIN / 2) + lhalf * 4;
    const int s_off = lrow * 8 + ((lhalf * 4) ^ (lrow & 4));

    const int lr = lane & 15, kq = lane >> 4;
    uint32_t off_a[2], off_b[4];
#pragma unroll
    for (int mt = 0; mt < 2; mt++) {
        int r = warpM * 32 + mt * 16 + lr;
        off_a[mt] = (uint32_t)(r * 8 + ((kq * 4) ^ (r & 4))) * 4u;
    }
#pragma unroll
    for (int np = 0; np < 4; np++) {
        int r = warpN * 64 + np * 16 + lr;
        off_b[np] = (uint32_t)(r * 8 + ((kq * 4) ^ (r & 4))) * 4u;
    }
    uint32_t baseA[2], baseB[2];
#pragma unroll
    for (int b = 0; b < 2; b++) {
        baseA[b] = (uint32_t)__cvta_generic_to_shared(&As[b][0]);
        baseB[b] = (uint32_t)__cvta_generic_to_shared(&Bs[b][0]);
    }

    float acc[2][8][4];
#pragma unroll
    for (int mt = 0; mt < 2; mt++)
#pragma unroll
        for (int nt = 0; nt < 8; nt++)
#pragma unroll
            for (int q = 0; q < 4; q++) acc[mt][nt][q] = 0.f;

    float4 xf0, xf1;
    uint4 rb;

    auto pack_store = [&](int buf, float4 f0, float4 f1) {
        uint4 hv;
        __nv_bfloat162 b0 = __floats2bfloat162_rn(f0.x, f0.y);
        __nv_bfloat162 b1 = __floats2bfloat162_rn(f0.z, f0.w);
        __nv_bfloat162 b2 = __floats2bfloat162_rn(f1.x, f1.y);
        __nv_bfloat162 b3 = __floats2bfloat162_rn(f1.z, f1.w);
        hv.x = *reinterpret_cast<uint32_t*>(&b0);
        hv.y = *reinterpret_cast<uint32_t*>(&b1);
        hv.z = *reinterpret_cast<uint32_t*>(&b2);
        hv.w = *reinterpret_cast<uint32_t*>(&b3);
        *(uint4*)&As[buf][s_off] = hv;
    };

    // prologue: stage 0
    xf0 = *(const float4*)&xrow[0];
    xf1 = *(const float4*)&xrow[4];
    rb  = *(const uint4*)&g_w1t[b_base];
    pack_store(0, xf0, xf1);
    *(uint4*)&Bs[0][s_off] = rb;
    __syncthreads();

    const int NSTAGE = FIN / 16;    // 32
    for (int ks = 0; ks < NSTAGE; ks++) {
        const int cur = ks & 1;
        if (ks + 1 < NSTAGE) {
            xf0 = *(const float4*)&xrow[(ks + 1) * 16];
            xf1 = *(const float4*)&xrow[(ks + 1) * 16 + 4];
            rb  = *(const uint4*)&g_w1t[b_base + (size_t)(ks + 1) * 8];
        }

        uint32_t af[2][4];
        ldm4(af[0], baseA[cur] + off_a[0]);
        ldm4(af[1], baseA[cur] + off_a[1]);

#pragma unroll
        for (int np = 0; np < 4; np++) {
            uint32_t bh[4];
            ldm4(bh, baseB[cur] + off_b[np]);
#pragma unroll
            for (int mt = 0; mt < 2; mt++) {
                MMA_BF16(acc[mt][2 * np],     af[mt][0], af[mt][1], af[mt][2], af[mt][3], bh[0], bh[2]);
                MMA_BF16(acc[mt][2 * np + 1], af[mt][0], af[mt][1], af[mt][2], af[mt][3], bh[1], bh[3]);
            }
        }
        if (ks + 1 < NSTAGE) {
            const int nxt = 1 - cur;
            pack_store(nxt, xf0, xf1);
            *(uint4*)&Bs[nxt][s_off] = rb;
            __syncthreads();
        }
    }

    // ---- epilogue: bf16 h1 store + fused alpha1 (2 heads per warp) -----------
#pragma unroll
    for (int mt = 0; mt < 2; mt++) {
        const int r0 = rowBase + warpM * 32 + mt * 16 + (lane >> 2);
        const int r1 = r0 + 8;
#pragma unroll
        for (int nt = 0; nt < 8; nt++) {
            const int c = colBase + warpN * 64 + nt * 8 + (lane & 3) * 2;
            if (r0 < NN) {
                __nv_bfloat162 bv = __floats2bfloat162_rn(acc[mt][nt][0], acc[mt][nt][1]);
                g_h1b[(size_t)r0 * (D1/2) + (c >> 1)] = *reinterpret_cast<uint32_t*>(&bv);
            }
            if (r1 < NN) {
                __nv_bfloat162 bv = __floats2bfloat162_rn(acc[mt][nt][2], acc[mt][nt][3]);
                g_h1b[(size_t)r1 * (D1/2) + (c >> 1)] = *reinterpret_cast<uint32_t*>(&bv);
            }
        }
#pragma unroll
        for (int hl = 0; hl < 2; hl++) {
            float ps0 = 0.f, pd0 = 0.f, ps1 = 0.f, pd1 = 0.f;
#pragma unroll
            for (int ntq = 0; ntq < 4; ntq++) {
                const int nt = hl * 4 + ntq;
                const int c = colBase + warpN * 64 + nt * 8 + (lane & 3) * 2;
                float av0 = __ldg(&a_src1[c]), av1 = __ldg(&a_src1[c + 1]);
                float dv0 = __ldg(&a_dst1[c]), dv1 = __ldg(&a_dst1[c + 1]);
                ps0 += acc[mt][nt][0] * av0 + acc[mt][nt][1] * av1;
                pd0 += acc[mt][nt][0] * dv0 + acc[mt][nt][1] * dv1;
                ps1 += acc[mt][nt][2] * av0 + acc[mt][nt][3] * av1;
                pd1 += acc[mt][nt][2] * dv0 + acc[mt][nt][3] * dv1;
            }
#pragma unroll
            for (int off = 1; off < 4; off <<= 1) {
                ps0 += __shfl_xor_sync(0xffffffffu, ps0, off);
                pd0 += __shfl_xor_sync(0xffffffffu, pd0, off);
                ps1 += __shfl_xor_sync(0xffffffffu, ps1, off);
                pd1 += __shfl_xor_sync(0xffffffffu, pd1, off);
            }
            if ((lane & 3) == 0) {
                const int hg = (colBase >> 5) + warpN * 2 + hl;
                if (r0 < NN) { g_as1[r0 * H1 + hg] = ps0; g_ad1[r0 * H1 + hg] = pd0; }
                if (r1 < NN) { g_as1[r1 * H1 + hg] = ps1; g_ad1[r1 * H1 + hg] = pd1; }
            }
        }
    }
}

// ---------------- CSR build ---------------------------------------------------
__global__ void zero_deg_kernel() {
    int i = blockIdx.x * blockDim.x + threadIdx.x;
    if (i < NN) g_deg[i] = 0;
}

__global__ void hist_kernel(const int* __restrict__ ei) {
    int i = blockIdx.x * blockDim.x + threadIdx.x;
    if (i >= E2) return;
    int d = (i < EE) ? __ldg(&ei[EE + i]) : (i - EE);
    atomicAdd(&g_deg[d], 1);
}

__global__ void scan_block_kernel() {
    __shared__ int sh[1024];
    int tid = threadIdx.x;
    int i = blockIdx.x * 1024 + tid;
    int v = (i < NN) ? g_deg[i] : 0;
    sh[tid] = v;
    __syncthreads();
#pragma unroll
    for (int off = 1; off < 1024; off <<= 1) {
        int t = (tid >= off) ? sh[tid - off] : 0;
        __syncthreads();
        sh[tid] += t;
        __syncthreads();
    }
    if (i < NN) g_incl[i] = sh[tid];
    if (tid == 1023) g_parts[blockIdx.x] = sh[tid];
}

__global__ void scan_parts_kernel(int nb) {
    __shared__ int sh[64];
    int tid = threadIdx.x;
    int v = (tid < nb) ? g_parts[tid] : 0;
    sh[tid] = v;
    __syncthreads();
#pragma unroll
    for (int off = 1; off < 64; off <<= 1) {
        int t = (tid >= off) ? sh[tid - off] : 0;
        __syncthreads();
        sh[tid] += t;
        __syncthreads();
    }
    if (tid < nb) g_parts_ex[tid] = sh[tid] - v;
}

__global__ void finalize_scan_kernel() {
    int i = blockIdx.x * blockDim.x + threadIdx.x;
    if (i >= NN) return;
    int start = g_incl[i] - g_deg[i] + g_parts_ex[i >> 10];
    g_starts[i] = start;
    g_cursor[i] = start;
}

__global__ void fill_kernel(const int* __restrict__ ei) {
    int i = blockIdx.x * blockDim.x + threadIdx.x;
    if (i >= E2) return;
    int s, d;
    if (i < EE) { s = __ldg(&ei[i]); d = __ldg(&ei[EE + i]); }
    else        { s = i - EE; d = s; }
    int p = atomicAdd(&g_cursor[d], 1);
    g_ssrc[p] = s;
}

// ---------------- layer1 aggregation (warp per dst node, bf16 gather) ---------
__global__ void agg1_kernel(const float* __restrict__ b1) {
    int n = (blockIdx.x * blockDim.x + threadIdx.x) >> 5;
    int lane = threadIdx.x & 31;
    if (n >= NN) return;
    int st = g_starts[n];
    int d  = g_deg[n];

    float4 adv0 = *(const float4*)&g_ad1[n * H1];
    float4 adv1 = *(const float4*)&g_ad1[n * H1 + 4];

    float den[H1];
#pragma unroll
    for (int h = 0; h < H1; h++) den[h] = 0.f;
    for (int j = lane; j < d; j += 32) {
        int s = __ldg(&g_ssrc[st + j]);
        float* wp = &g_wbuf[(size_t)(st + j) * H1];
        const float4* ap = (const float4*)&g_as1[s * H1];
        float4 a0 = __ldg(ap), a1 = __ldg(ap + 1);
        float e[H1];
        e[0] = a0.x + adv0.x;  e[1] = a0.y + adv0.y;
        e[2] = a0.z + adv0.z;  e[3] = a0.w + adv0.w;
        e[4] = a1.x + adv1.x;  e[5] = a1.y + adv1.y;
        e[6] = a1.z + adv1.z;  e[7] = a1.w + adv1.w;
#pragma unroll
        for (int h = 0; h < H1; h++) {
            float ee = fmaxf(e[h], 0.2f * e[h]);
            float ex = __expf(ee);
            wp[h] = ex;
            den[h] += ex;
        }
    }
#pragma unroll
    for (int h = 0; h < H1; h++) {
#pragma unroll
        for (int off = 16; off > 0; off >>= 1)
            den[h] += __shfl_xor_sync(0xffffffffu, den[h], off);
    }
    float inv[H1];
#pragma unroll
    for (int h = 0; h < H1; h++) inv[h] = 1.f / (den[h] + 1e-16f);

    float invq[4];
#pragma unroll
    for (int q = 0; q < 4; q++)
        invq[q] = (lane >= 16) ? inv[2 * q + 1] : inv[2 * q];
    const int hsel = lane >> 4;

    float2 acc2[4];
#pragma unroll
    for (int q = 0; q < 4; q++) acc2[q] = make_float2(0.f, 0.f);
#pragma unroll 4
    for (int j = 0; j < d; j++) {
        int s = __ldg(&g_ssrc[st + j]);
        const float* wp = &g_wbuf[(size_t)(st + j) * H1];
        const uint32_t* hb = &g_h1b[(size_t)s * (D1/2)];
#pragma unroll
        for (int q = 0; q < 4; q++) {
            float w = wp[2 * q + hsel] * invq[q];
            uint32_t u = __ldg(&hb[32 * q + lane]);
            __nv_bfloat162 bv = *reinterpret_cast<__nv_bfloat162*>(&u);
            float2 f = __bfloat1622float2(bv);
            acc2[q].x = fmaf(f.x, w, acc2[q].x);
            acc2[q].y = fmaf(f.y, w, acc2[q].y);
        }
    }

#pragma unroll
    for (int q = 0; q < 4; q++) {
        int c0 = (32 * q + lane) * 2;
        float2 bb = *(const float2*)&b1[c0];
        float v0 = acc2[q].x + bb.x;
        float v1 = acc2[q].y + bb.y;
        v0 = (v0 > 0.f) ? v0 : expm1f(v0);
        v1 = (v1 > 0.f) ? v1 : expm1f(v1);
        *(float2*)&g_hout1[(size_t)n * D1 + c0] = make_float2(v0, v1);
    }
}

// ---------------- layer2 linear + alpha2 (bf16x2 packed output) ---------------
__global__ void layer2_linear_kernel(const float* __restrict__ W2,
                                     const float* __restrict__ a_src2,
                                     const float* __restrict__ a_dst2) {
    __shared__ float Ws[D1 * CLS + 64];
    __shared__ float as_sh[CLS], ad_sh[CLS];
    int tid = threadIdx.x;
    for (int i = tid; i < D1 * CLS + 64; i += blockDim.x)
        Ws[i] = (i < D1 * CLS) ? W2[i] : 0.f;
    if (tid < CLS) { as_sh[tid] = a_src2[tid]; ad_sh[tid] = a_dst2[tid]; }
    __syncthreads();

    int lane = tid & 31;
    int warpsPerBlock = blockDim.x >> 5;
    int gw = blockIdx.x * warpsPerBlock + (tid >> 5);
    int stride = gridDim.x * warpsPerBlock;

    for (int n = gw; n < NN; n += stride) {
        const float* xp = &g_hout1[(size_t)n * D1];
        float acc0a = 0.f, acc0b = 0.f, acc1a = 0.f, acc1b = 0.f;
#pragma unroll
        for (int kb = 0; kb < D1 / 32; kb++) {
            float xv = xp[kb * 32 + lane];
#pragma unroll
            for (int j = 0; j < 32; j += 2) {
                float xj0 = __shfl_sync(0xffffffffu, xv, j);
                float xj1 = __shfl_sync(0xffffffffu, xv, j + 1);
                int k0 = kb * 32 + j;
                acc0a = fmaf(xj0, Ws[k0 * CLS + lane], acc0a);
                acc1a = fmaf(xj0, Ws[k0 * CLS + 32 + lane], acc1a);
                acc0b = fmaf(xj1, Ws[(k0 + 1) * CLS + lane], acc0b);
                acc1b = fmaf(xj1, Ws[(k0 + 1) * CLS + 32 + lane], acc1b);
            }
        }
        float v0 = acc0a + acc0b;
        float v1 = acc1a + acc1b;

        float v0n = __shfl_down_sync(0xffffffffu, v0, 1);
        float v1n = __shfl_down_sync(0xffffffffu, v1, 1);
        if ((lane & 1) == 0) {
            __nv_bfloat162 bv = __floats2bfloat162_rn(v0, v0n);
            g_h2b[(size_t)n * C2P + (lane >> 1)] = *reinterpret_cast<uint32_t*>(&bv);
            if (lane < 8) {
                __nv_bfloat162 bw = __floats2bfloat162_rn(v1, v1n);
                g_h2b[(size_t)n * C2P + 16 + (lane >> 1)] = *reinterpret_cast<uint32_t*>(&bw);
            }
        }

        float ps = v0 * as_sh[lane] + ((lane < CLS - 32) ? v1 * as_sh[32 + lane] : 0.f);
        float pd = v0 * ad_sh[lane] + ((lane < CLS - 32) ? v1 * ad_sh[32 + lane] : 0.f);
#pragma unroll
        for (int off = 16; off > 0; off >>= 1) {
            ps += __shfl_xor_sync(0xffffffffu, ps, off);
            pd += __shfl_xor_sync(0xffffffffu, pd, off);
        }
        if (lane == 0) { g_as2[n] = ps; g_ad2[n] = pd; }
    }
}

// ---------------- layer2 aggregation + log_softmax (bf16 gather) --------------
__global__ void agg2_kernel(const float* __restrict__ b2, float* __restrict__ out) {
    int n = (blockIdx.x * blockDim.x + threadIdx.x) >> 5;
    int lane = threadIdx.x & 31;
    if (n >= NN) return;
    int st = g_starts[n];
    int d  = g_deg[n];
    float adn = g_ad2[n];

    float den = 0.f;
    for (int j = lane; j < d; j += 32) {
        int s = __ldg(&g_ssrc[st + j]);
        float e = __ldg(&g_as2[s]) + adn;
        e = fmaxf(e, 0.2f * e);
        float ex = __expf(e);
        g_wbuf2[st + j] = ex;
        den += ex;
    }
#pragma unroll
    for (int off = 16; off > 0; off >>= 1)
        den += __shfl_xor_sync(0xffffffffu, den, off);
    float inv = 1.f / (den + 1e-16f);

    float2 acc2 = make_float2(0.f, 0.f);
#pragma unroll 4
    for (int j = 0; j < d; j++) {
        int s = __ldg(&g_ssrc[st + j]);
        float w = g_wbuf2[st + j] * inv;
        if (lane < 20) {
            uint32_t u = __ldg(&g_h2b[(size_t)s * C2P + lane]);
            __nv_bfloat162 bv = *reinterpret_cast<__nv_bfloat162*>(&u);
            float2 f = __bfloat1622float2(bv);
            acc2.x = fmaf(f.x, w, acc2.x);
            acc2.y = fmaf(f.y, w, acc2.y);
        }
    }

    float2 vv = make_float2(-CUDART_INF_F, -CUDART_INF_F);
    if (lane < 20) {
        float2 bb = *(const float2*)&b2[2 * lane];
        vv.x = acc2.x + bb.x;
        vv.y = acc2.y + bb.y;
    }

    float m = fmaxf(vv.x, vv.y);
#pragma unroll
    for (int off = 16; off > 0; off >>= 1)
        m = fmaxf(m, __shfl_xor_sync(0xffffffffu, m, off));
    float s0 = (lane < 20) ? (__expf(vv.x - m) + __expf(vv.y - m)) : 0.f;
#pragma unroll
    for (int off = 16; off > 0; off >>= 1)
        s0 += __shfl_xor_sync(0xffffffffu, s0, off);
    float lse = m + logf(s0);

    if (lane < 20)
        *(float2*)&out[(size_t)n * CLS + 2 * lane] = make_float2(vv.x - lse, vv.y - lse);
}

// ---------------- launch ------------------------------------------------------
extern "C" void kernel_launch(void* const* d_in, const int* in_sizes, int n_in,
                              void* d_out, int out_size) {
    const float* x      = (const float*)d_in[0];
    const int*   ei     = (const int*)d_in[1];
    const float* W1     = (const float*)d_in[2];
    const float* a_src1 = (const float*)d_in[3];
    const float* a_dst1 = (const float*)d_in[4];
    const float* b1     = (const float*)d_in[5];
    const float* W2     = (const float*)d_in[6];
    const float* a_src2 = (const float*)d_in[7];
    const float* a_dst2 = (const float*)d_in[8];
    const float* b2     = (const float*)d_in[9];
    float* out = (float*)d_out;

    const int nb_scan = (NN + 1023) / 1024;   // 49

    static cudaStream_t s2 = nullptr;
    static cudaEvent_t evFork = nullptr, evCSR = nullptr;
    if (s2 == nullptr) {
        cudaStreamCreateWithFlags(&s2, cudaStreamNonBlocking);
        cudaEventCreateWithFlags(&evFork, cudaEventDisableTiming);
        cudaEventCreateWithFlags(&evCSR, cudaEventDisableTiming);
    }

    // launch #1 (main): W1 pack (tiny; GEMM depends on it in-stream)
    prep_w_kernel<<<(D1 * (FIN / 2) + 255) / 256, 256>>>(W1);

    // fork: CSR chain on side stream
    cudaEventRecord(evFork, 0);
    cudaStreamWaitEvent(s2, evFork, 0);
    zero_deg_kernel<<<(NN + 255) / 256, 256, 0, s2>>>();
    hist_kernel<<<(E2 + 255) / 256, 256, 0, s2>>>(ei);
    scan_block_kernel<<<nb_scan, 1024, 0, s2>>>();
    scan_parts_kernel<<<1, 64, 0, s2>>>(nb_scan);

    // launch #6 (main): GEMM + fused alpha1 — in the ncu capture window
    sgemm1_tc_kernel<<<dim3(2, (NN + 127) / 128), 256>>>(x, a_src1, a_dst1);

    finalize_scan_kernel<<<(NN + 255) / 256, 256, 0, s2>>>();
    fill_kernel<<<(E2 + 255) / 256, 256, 0, s2>>>(ei);
    cudaEventRecord(evCSR, s2);

    // join: agg1 needs CSR + GEMM(alpha1)
    cudaStreamWaitEvent(0, evCSR, 0);
    agg1_kernel<<<(NN * 32 + 255) / 256, 256>>>(b1);

    // layer 2
    layer2_linear_kernel<<<592, 256>>>(W2, a_src2, a_dst2);
    agg2_kernel<<<(NN * 32 + 255) / 256, 256>>>(b2, out);
}